// round 7
// baseline (speedup 1.0000x reference)
#include <cuda_runtime.h>
#include <math.h>
#include <stddef.h>

// ---------------- problem constants ----------------
#define Bdim 32
#define Tdim 12
#define Ndim 325
#define Ddim 128
#define Hdim 8
#define Fdim 512
#define BTN  124800          // B*T*N tokens
#define BNSEQ 10400          // B*N temporal sequences
#define BTSEQ 384            // B*T spatial sequences

typedef unsigned long long u64;

// ---------------- packed f32x2 helpers (FFMA2 pipe) ----------------
__device__ __forceinline__ u64 pack2(float lo, float hi) {
    u64 r; asm("mov.b64 %0, {%1, %2};" : "=l"(r) : "f"(lo), "f"(hi)); return r;
}
__device__ __forceinline__ void ffma2(u64& d, u64 a, u64 b) {
    asm("fma.rn.f32x2 %0, %1, %2, %0;" : "+l"(d) : "l"(a), "l"(b));
}
__device__ __forceinline__ float2 unpack2(u64 v) {
    float2 r; asm("mov.b64 {%0, %1}, %2;" : "=f"(r.x), "=f"(r.y) : "l"(v)); return r;
}

// ---------------- scratch (no-alloc rule: __device__ globals) ----------------
static __device__ float g_qkv [(size_t)BTN * 384];
static __device__ float g_attn[(size_t)BTN * 128];
static __device__ float g_x1  [(size_t)BTN * 128];
static __device__ float g_x2  [(size_t)BTN * 128];
static __device__ float g_hbuf[(size_t)BTN * 512];

__device__ __forceinline__ float gelu_tanh(float v) {
    float c = 0.7978845608028654f * (v + 0.044715f * v * v * v);
    return 0.5f * v * (1.0f + tanhf(c));
}

// ---------------- register-tiled SGEMM (f32x2): C[M,Nc] = A[M,KD] @ W[Nc,KD]^T + bias ----
#define GBM 128
#define GBN 128
#define GBK 16

template <int KD, bool DOGELU>
__global__ __launch_bounds__(256, 2) void gemm_bias_kernel(
    const float* __restrict__ A, const float* __restrict__ W,
    const float* __restrict__ bias, float* __restrict__ C, int Nc)
{
    __shared__ __align__(16) float As[GBK][GBM];
    __shared__ __align__(16) float Ws[GBK][GBN];
    const int mblk = blockIdx.y * GBM;
    const int nblk = blockIdx.x * GBN;
    const int tid  = threadIdx.x;
    const int tx   = tid & 15;
    const int ty   = tid >> 4;

    const int f0 = tid, f1 = tid + 256;
    const int r0 = f0 >> 2, kq0 = (f0 & 3) << 2;
    const int r1 = f1 >> 2, kq1 = (f1 & 3) << 2;

    u64 acc2[8][4];
#pragma unroll
    for (int i = 0; i < 8; i++)
#pragma unroll
        for (int jp = 0; jp < 4; jp++) acc2[i][jp] = 0ULL;

    // prefetch k0 = 0
    float4 pa0 = *(const float4*)(A + (size_t)(mblk + r0) * KD + kq0);
    float4 pa1 = *(const float4*)(A + (size_t)(mblk + r1) * KD + kq1);
    float4 pw0 = *(const float4*)(W + (size_t)(nblk + r0) * KD + kq0);
    float4 pw1 = *(const float4*)(W + (size_t)(nblk + r1) * KD + kq1);

    for (int k0 = 0; k0 < KD; k0 += GBK) {
        As[kq0 + 0][r0] = pa0.x; As[kq0 + 1][r0] = pa0.y;
        As[kq0 + 2][r0] = pa0.z; As[kq0 + 3][r0] = pa0.w;
        As[kq1 + 0][r1] = pa1.x; As[kq1 + 1][r1] = pa1.y;
        As[kq1 + 2][r1] = pa1.z; As[kq1 + 3][r1] = pa1.w;
        Ws[kq0 + 0][r0] = pw0.x; Ws[kq0 + 1][r0] = pw0.y;
        Ws[kq0 + 2][r0] = pw0.z; Ws[kq0 + 3][r0] = pw0.w;
        Ws[kq1 + 0][r1] = pw1.x; Ws[kq1 + 1][r1] = pw1.y;
        Ws[kq1 + 2][r1] = pw1.z; Ws[kq1 + 3][r1] = pw1.w;
        __syncthreads();

        if (k0 + GBK < KD) {  // prefetch next tile (overlaps with compute)
            int kn = k0 + GBK;
            pa0 = *(const float4*)(A + (size_t)(mblk + r0) * KD + kn + kq0);
            pa1 = *(const float4*)(A + (size_t)(mblk + r1) * KD + kn + kq1);
            pw0 = *(const float4*)(W + (size_t)(nblk + r0) * KD + kn + kq0);
            pw1 = *(const float4*)(W + (size_t)(nblk + r1) * KD + kn + kq1);
        }

#pragma unroll
        for (int kk = 0; kk < GBK; kk++) {
            float a[8];
            *(float4*)&a[0] = *(const float4*)&As[kk][ty * 8];
            *(float4*)&a[4] = *(const float4*)&As[kk][ty * 8 + 4];
            u64 w2[4];
            *(float4*)&w2[0] = *(const float4*)&Ws[kk][tx * 8];
            *(float4*)&w2[2] = *(const float4*)&Ws[kk][tx * 8 + 4];
#pragma unroll
            for (int i = 0; i < 8; i++) {
                u64 a2 = pack2(a[i], a[i]);
#pragma unroll
                for (int jp = 0; jp < 4; jp++) ffma2(acc2[i][jp], a2, w2[jp]);
            }
        }
        __syncthreads();
    }

    // unpack + epilogue
#pragma unroll
    for (int i = 0; i < 8; i++) {
        size_t row = (size_t)(mblk + ty * 8 + i) * Nc;
#pragma unroll
        for (int jp = 0; jp < 4; jp += 2) {
            int n = nblk + tx * 8 + jp * 2;
            float4 bb = *(const float4*)(bias + n);
            float2 p0 = unpack2(acc2[i][jp]);
            float2 p1 = unpack2(acc2[i][jp + 1]);
            float4 o;
            o.x = p0.x + bb.x; o.y = p0.y + bb.y;
            o.z = p1.x + bb.z; o.w = p1.y + bb.w;
            if (DOGELU) {
                o.x = gelu_tanh(o.x); o.y = gelu_tanh(o.y);
                o.z = gelu_tanh(o.z); o.w = gelu_tanh(o.w);
            }
            *(float4*)(C + row + n) = o;
        }
    }
}

// ---------------- SGEMM + bias + residual + LayerNorm (f32x2), Nc = 128 fixed ----------------
template <int KD>
__global__ __launch_bounds__(256, 2) void gemm_res_ln_kernel(
    const float* __restrict__ A, const float* __restrict__ W,
    const float* __restrict__ bias, const float* __restrict__ res,
    const float* __restrict__ gam, const float* __restrict__ bet,
    float* __restrict__ C)
{
    __shared__ __align__(16) float As[GBK][GBM];
    __shared__ __align__(16) float Ws[GBK][128];
    __shared__ float redS[GBM][17];
    __shared__ float redQ[GBM][17];
    __shared__ float sMean[GBM];
    __shared__ float sRstd[GBM];

    const int mblk = blockIdx.x * GBM;
    const int tid  = threadIdx.x;
    const int tx   = tid & 15;
    const int ty   = tid >> 4;

    const int f0 = tid, f1 = tid + 256;
    const int r0 = f0 >> 2, kq0 = (f0 & 3) << 2;
    const int r1 = f1 >> 2, kq1 = (f1 & 3) << 2;

    u64 acc2[8][4];
#pragma unroll
    for (int i = 0; i < 8; i++)
#pragma unroll
        for (int jp = 0; jp < 4; jp++) acc2[i][jp] = 0ULL;

    float4 pa0 = *(const float4*)(A + (size_t)(mblk + r0) * KD + kq0);
    float4 pa1 = *(const float4*)(A + (size_t)(mblk + r1) * KD + kq1);
    float4 pw0 = *(const float4*)(W + (size_t)r0 * KD + kq0);
    float4 pw1 = *(const float4*)(W + (size_t)r1 * KD + kq1);

    for (int k0 = 0; k0 < KD; k0 += GBK) {
        As[kq0 + 0][r0] = pa0.x; As[kq0 + 1][r0] = pa0.y;
        As[kq0 + 2][r0] = pa0.z; As[kq0 + 3][r0] = pa0.w;
        As[kq1 + 0][r1] = pa1.x; As[kq1 + 1][r1] = pa1.y;
        As[kq1 + 2][r1] = pa1.z; As[kq1 + 3][r1] = pa1.w;
        Ws[kq0 + 0][r0] = pw0.x; Ws[kq0 + 1][r0] = pw0.y;
        Ws[kq0 + 2][r0] = pw0.z; Ws[kq0 + 3][r0] = pw0.w;
        Ws[kq1 + 0][r1] = pw1.x; Ws[kq1 + 1][r1] = pw1.y;
        Ws[kq1 + 2][r1] = pw1.z; Ws[kq1 + 3][r1] = pw1.w;
        __syncthreads();

        if (k0 + GBK < KD) {
            int kn = k0 + GBK;
            pa0 = *(const float4*)(A + (size_t)(mblk + r0) * KD + kn + kq0);
            pa1 = *(const float4*)(A + (size_t)(mblk + r1) * KD + kn + kq1);
            pw0 = *(const float4*)(W + (size_t)r0 * KD + kn + kq0);
            pw1 = *(const float4*)(W + (size_t)r1 * KD + kn + kq1);
        }

#pragma unroll
        for (int kk = 0; kk < GBK; kk++) {
            float a[8];
            *(float4*)&a[0] = *(const float4*)&As[kk][ty * 8];
            *(float4*)&a[4] = *(const float4*)&As[kk][ty * 8 + 4];
            u64 w2[4];
            *(float4*)&w2[0] = *(const float4*)&Ws[kk][tx * 8];
            *(float4*)&w2[2] = *(const float4*)&Ws[kk][tx * 8 + 4];
#pragma unroll
            for (int i = 0; i < 8; i++) {
                u64 a2 = pack2(a[i], a[i]);
#pragma unroll
                for (int jp = 0; jp < 4; jp++) ffma2(acc2[i][jp], a2, w2[jp]);
            }
        }
        __syncthreads();
    }

    // unpack into float accumulators (acc2 dies here; regs reused)
    float acc[8][8];
#pragma unroll
    for (int i = 0; i < 8; i++)
#pragma unroll
        for (int jp = 0; jp < 4; jp++) {
            float2 p = unpack2(acc2[i][jp]);
            acc[i][jp * 2] = p.x; acc[i][jp * 2 + 1] = p.y;
        }

    // bias + residual + row partial sums
#pragma unroll
    for (int i = 0; i < 8; i++) {
        int lr = ty * 8 + i;
        int m  = mblk + lr;
        const float* rrow = res + (size_t)m * 128 + tx * 8;
        float4 rr0 = *(const float4*)(rrow);
        float4 rr1 = *(const float4*)(rrow + 4);
        float4 b0 = *(const float4*)(bias + tx * 8);
        float4 b1 = *(const float4*)(bias + tx * 8 + 4);
        acc[i][0] += b0.x + rr0.x; acc[i][1] += b0.y + rr0.y;
        acc[i][2] += b0.z + rr0.z; acc[i][3] += b0.w + rr0.w;
        acc[i][4] += b1.x + rr1.x; acc[i][5] += b1.y + rr1.y;
        acc[i][6] += b1.z + rr1.z; acc[i][7] += b1.w + rr1.w;
        float s = 0.0f, qq = 0.0f;
#pragma unroll
        for (int j = 0; j < 8; j++) { s += acc[i][j]; qq = fmaf(acc[i][j], acc[i][j], qq); }
        redS[lr][tx] = s;
        redQ[lr][tx] = qq;
    }
    __syncthreads();
    if (tid < 128) {
        float s = 0.0f, qq = 0.0f;
#pragma unroll
        for (int c = 0; c < 16; c++) { s += redS[tid][c]; qq += redQ[tid][c]; }
        float mean = s * (1.0f / 128.0f);
        float var  = qq * (1.0f / 128.0f) - mean * mean;
        sMean[tid] = mean;
        sRstd[tid] = rsqrtf(var + 1e-5f);
    }
    __syncthreads();
#pragma unroll
    for (int i = 0; i < 8; i++) {
        int lr = ty * 8 + i;
        float mean = sMean[lr], rstd = sRstd[lr];
        size_t row = (size_t)(mblk + lr) * 128;
#pragma unroll
        for (int j4 = 0; j4 < 8; j4 += 4) {
            int n = tx * 8 + j4;
            float4 g4 = *(const float4*)(gam + n);
            float4 b4 = *(const float4*)(bet + n);
            float4 o;
            o.x = (acc[i][j4 + 0] - mean) * rstd * g4.x + b4.x;
            o.y = (acc[i][j4 + 1] - mean) * rstd * g4.y + b4.y;
            o.z = (acc[i][j4 + 2] - mean) * rstd * g4.z + b4.z;
            o.w = (acc[i][j4 + 3] - mean) * rstd * g4.w + b4.w;
            *(float4*)(C + row + n) = o;
        }
    }
}

// ---------------- temporal attention: one block per (b, n) sequence, T=12 ----------------
__global__ __launch_bounds__(128) void temporal_attn_kernel(
    const float* __restrict__ qkv, float* __restrict__ attn)
{
    __shared__ __align__(16) float sq[Tdim][388];
    const int bn  = blockIdx.x;
    const int b   = bn / Ndim;
    const int n   = bn % Ndim;
    const int tid = threadIdx.x;

    for (int idx = tid; idx < Tdim * 96; idx += 128) {
        int t = idx / 96;
        int c = (idx % 96) * 4;
        size_t r = ((size_t)(b * Tdim + t) * Ndim + n) * 384;
        *(float4*)&sq[t][c] = *(const float4*)(qkv + r + c);
    }
    __syncthreads();

    if (tid < Hdim * Tdim) {
        const int h   = tid / Tdim;
        const int q   = tid % Tdim;
        const int off = h * 16;
        float qd[16];
#pragma unroll
        for (int d = 0; d < 16; d++) qd[d] = sq[q][off + d];

        float e[Tdim];
        float Z = 0.0f;
#pragma unroll
        for (int s = 0; s < Tdim; s++) {
            float sc = 0.0f;
#pragma unroll
            for (int d = 0; d < 16; d++) sc = fmaf(qd[d], sq[s][128 + off + d], sc);
            e[s] = __expf(sc * 0.25f);
            Z += e[s];
        }
        float inv = 1.0f / Z;
        float o[16];
#pragma unroll
        for (int d = 0; d < 16; d++) {
            float a = 0.0f;
#pragma unroll
            for (int s = 0; s < Tdim; s++) a = fmaf(e[s], sq[s][256 + off + d], a);
            o[d] = a * inv;
        }
        size_t ro = ((size_t)(b * Tdim + q) * Ndim + n) * 128 + off;
#pragma unroll
        for (int c = 0; c < 16; c += 4) {
            float4 v; v.x = o[c]; v.y = o[c + 1]; v.z = o[c + 2]; v.w = o[c + 3];
            *(float4*)(attn + ro + c) = v;
        }
    }
}

// ---------------- spatial attention (f32x2): one block per (bt, head) ----------------
__global__ __launch_bounds__(352) void spatial_attn_kernel(
    const float* __restrict__ qkv, const float* __restrict__ gbias,
    float* __restrict__ attn)
{
    __shared__ __align__(16) float Ks[Ndim][16];
    __shared__ __align__(16) float Vs[Ndim][16];
    const int h   = blockIdx.x;
    const int bt  = blockIdx.y;
    const int tid = threadIdx.x;
    const size_t base = (size_t)bt * Ndim * 384;
    const int off = h * 16;

    for (int idx = tid; idx < Ndim * 4; idx += 352) {
        int j = idx >> 2;
        int c = (idx & 3) << 2;
        const float* p = qkv + base + (size_t)j * 384 + 128 + off + c;
        *(float4*)&Ks[j][c] = *(const float4*)p;
        *(float4*)&Vs[j][c] = *(const float4*)(p + 128);
    }
    __syncthreads();

    const int  q     = tid;
    const bool valid = (q < Ndim);
    const int  qc    = valid ? q : 0;

    u64 qr2[8];
    const float* qp = qkv + base + (size_t)qc * 384 + off;
#pragma unroll
    for (int c = 0; c < 4; c++)
        *(float4*)&qr2[c * 2] = *(const float4*)(qp + c * 4);
    const float* brow = gbias + (size_t)qc * Ndim;

    float Z = 0.0f;
    u64 acc2[8];
#pragma unroll
    for (int d = 0; d < 8; d++) acc2[d] = 0ULL;

    for (int j = 0; j < Ndim; j++) {
        u64 k2[8];
#pragma unroll
        for (int c = 0; c < 4; c++)
            *(float4*)&k2[c * 2] = *(const float4*)&Ks[j][c * 4];
        u64 s2 = 0ULL;
#pragma unroll
        for (int c = 0; c < 8; c++) ffma2(s2, qr2[c], k2[c]);
        float2 sp = unpack2(s2);
        float e = __expf(fmaf(sp.x + sp.y, 0.25f, __ldg(brow + j)));
        Z += e;
        u64 e2 = pack2(e, e);
        u64 v2[8];
#pragma unroll
        for (int c = 0; c < 4; c++)
            *(float4*)&v2[c * 2] = *(const float4*)&Vs[j][c * 4];
#pragma unroll
        for (int c = 0; c < 8; c++) ffma2(acc2[c], e2, v2[c]);
    }

    if (valid) {
        float inv = 1.0f / Z;
        float* op = attn + ((size_t)bt * Ndim + q) * 128 + off;
#pragma unroll
        for (int c = 0; c < 4; c++) {
            float2 p0 = unpack2(acc2[c * 2]);
            float2 p1 = unpack2(acc2[c * 2 + 1]);
            float4 o;
            o.x = p0.x * inv; o.y = p0.y * inv;
            o.z = p1.x * inv; o.w = p1.y * inv;
            *(float4*)(op + c * 4) = o;
        }
    }
}

// ---------------- launch ----------------
extern "C" void kernel_launch(void* const* d_in, const int* in_sizes, int n_in,
                              void* d_out, int out_size)
{
    const float* x       = (const float*)d_in[0];
    const float* t_w_in  = (const float*)d_in[1];
    const float* t_b_in  = (const float*)d_in[2];
    const float* t_w_out = (const float*)d_in[3];
    const float* t_b_out = (const float*)d_in[4];
    const float* s_w_in  = (const float*)d_in[5];
    const float* s_b_in  = (const float*)d_in[6];
    const float* s_w_out = (const float*)d_in[7];
    const float* s_b_out = (const float*)d_in[8];
    const float* gbias   = (const float*)d_in[9];
    const float* ntg     = (const float*)d_in[10];
    const float* ntb     = (const float*)d_in[11];
    const float* nsg     = (const float*)d_in[12];
    const float* nsb     = (const float*)d_in[13];
    const float* ffw1    = (const float*)d_in[14];
    const float* ffb1    = (const float*)d_in[15];
    const float* ffw2    = (const float*)d_in[16];
    const float* ffb2    = (const float*)d_in[17];
    const float* nfg     = (const float*)d_in[18];
    const float* nfb     = (const float*)d_in[19];
    float* out = (float*)d_out;

    float *qkv, *attn, *x1, *x2, *hbuf;
    cudaGetSymbolAddress((void**)&qkv,  g_qkv);
    cudaGetSymbolAddress((void**)&attn, g_attn);
    cudaGetSymbolAddress((void**)&x1,   g_x1);
    cudaGetSymbolAddress((void**)&x2,   g_x2);
    cudaGetSymbolAddress((void**)&hbuf, g_hbuf);

    const int MT = BTN / GBM;   // 975

    gemm_bias_kernel<128, false><<<dim3(3, MT), 256>>>(x, t_w_in, t_b_in, qkv, 384);
    temporal_attn_kernel<<<BNSEQ, 128>>>(qkv, attn);
    gemm_res_ln_kernel<128><<<MT, 256>>>(attn, t_w_out, t_b_out, x, ntg, ntb, x1);
    gemm_bias_kernel<128, false><<<dim3(3, MT), 256>>>(x1, s_w_in, s_b_in, qkv, 384);
    spatial_attn_kernel<<<dim3(Hdim, BTSEQ), 352>>>(qkv, gbias, attn);
    gemm_res_ln_kernel<128><<<MT, 256>>>(attn, s_w_out, s_b_out, x1, nsg, nsb, x2);
    gemm_bias_kernel<128, true><<<dim3(4, MT), 256>>>(x2, ffw1, ffb1, hbuf, 512);
    gemm_res_ln_kernel<512><<<MT, 256>>>(hbuf, ffw2, ffb2, x2, nfg, nfb, out);
}

// round 11
// speedup vs baseline: 1.3185x; 1.3185x over previous
#include <cuda_runtime.h>
#include <cuda_bf16.h>
#include <math.h>
#include <stddef.h>
#include <stdint.h>

// ---------------- problem constants ----------------
#define Bdim 32
#define Tdim 12
#define Ndim 325
#define Ddim 128
#define Hdim 8
#define Fdim 512
#define BTN  124800          // B*T*N tokens
#define BNSEQ 10400          // B*N temporal sequences
#define BTSEQ 384            // B*T spatial sequences
#define MTILES 975           // BTN / 128

// ---------------- scratch (no-alloc rule: __device__ globals) ----------------
static __device__ float g_qkv[(size_t)BTN * 384];
static __device__ float g_x1f[(size_t)BTN * 128];
static __device__ float g_x2f[(size_t)BTN * 128];
static __device__ __nv_bfloat16 g_xhi[(size_t)BTN * 128];
static __device__ __nv_bfloat16 g_xlo[(size_t)BTN * 128];
static __device__ __nv_bfloat16 g_ahi[(size_t)BTN * 128];
static __device__ __nv_bfloat16 g_alo[(size_t)BTN * 128];
static __device__ __nv_bfloat16 g_bhi[(size_t)BTN * 128];
static __device__ __nv_bfloat16 g_blo[(size_t)BTN * 128];
static __device__ __nv_bfloat16 g_hhi[(size_t)BTN * 512];
static __device__ __nv_bfloat16 g_hlo[(size_t)BTN * 512];
static __device__ __nv_bfloat16 g_whi[262144];
static __device__ __nv_bfloat16 g_wlo[262144];
// weight offsets inside g_whi/g_wlo (elements)
#define WOFF_TIN  0
#define WOFF_SIN  49152
#define WOFF_TOUT 98304
#define WOFF_SOUT 114688
#define WOFF_FF1  131072
#define WOFF_FF2  196608

// ---------------- helpers ----------------
__device__ __forceinline__ uint32_t smem_u32(const void* p) {
    uint32_t a;
    asm("{ .reg .u64 t; cvta.to.shared.u64 t, %1; cvt.u32.u64 %0, t; }" : "=r"(a) : "l"(p));
    return a;
}
__device__ __forceinline__ void split1(float x, __nv_bfloat16& h, __nv_bfloat16& l) {
    h = __float2bfloat16(x);
    l = __float2bfloat16(x - __bfloat162float(h));
}
__device__ __forceinline__ float gelu_tanh(float v) {
    float c = 0.7978845608028654f * (v + 0.044715f * v * v * v);
    return 0.5f * v * (1.0f + tanhf(c));
}
__device__ __forceinline__ void ldm4(uint32_t* r, uint32_t addr) {
    asm volatile("ldmatrix.sync.aligned.m8n8.x4.shared.b16 {%0,%1,%2,%3}, [%4];"
                 : "=r"(r[0]), "=r"(r[1]), "=r"(r[2]), "=r"(r[3]) : "r"(addr));
}
__device__ __forceinline__ void mma_bf16(float* c, const uint32_t* a, const uint32_t* b) {
    asm volatile(
        "mma.sync.aligned.m16n8k16.row.col.f32.bf16.bf16.f32 "
        "{%0,%1,%2,%3}, {%4,%5,%6,%7}, {%8,%9}, {%0,%1,%2,%3};"
        : "+f"(c[0]), "+f"(c[1]), "+f"(c[2]), "+f"(c[3])
        : "r"(a[0]), "r"(a[1]), "r"(a[2]), "r"(a[3]), "r"(b[0]), "r"(b[1]));
}
__device__ __forceinline__ void cp16(uint32_t s, const void* g) {
    asm volatile("cp.async.cg.shared.global [%0], [%1], 16;" :: "r"(s), "l"(g));
}

// ---------------- split-bf16 HMMA GEMM ----------------
// C[M,Nc] = (Ahi+Alo)[M,KD] @ (Whi+Wlo)[Nc,KD]^T   (3-product split, fp32 accum)
// EPI 0: out = D + bias (fp32)
// EPI 1: out = gelu(D + bias) -> split bf16 hi/lo
// EPI 2: out = LN(D + bias + res) -> fp32 (+ split hi/lo if WSPLIT); Nc==128, nblk==0
//
// smem: two 40960B chunk buffers (4 tiles of 128 rows x 80B, bf16 k=32 chunk),
// reused at the end as a 128x132 fp32 staging tile + LN reduction scratch.
#define ROWB   80                 // smem bytes per tile row (64 data + 16 pad)
#define TILEB  10240              // 128 * 80
#define BUFB   40960              // 4 tiles
#define SMEM_DYN 81920            // 2 buffers

template <int KD, int EPI, bool WSPLIT>
__global__ __launch_bounds__(256) void mm_kernel(
    const __nv_bfloat16* __restrict__ Ahi, const __nv_bfloat16* __restrict__ Alo,
    const __nv_bfloat16* __restrict__ Whi, const __nv_bfloat16* __restrict__ Wlo,
    const float* __restrict__ bias,
    const float* __restrict__ res, const float* __restrict__ gam, const float* __restrict__ bet,
    float* __restrict__ outF, __nv_bfloat16* __restrict__ outHi, __nv_bfloat16* __restrict__ outLo,
    int Nc)
{
    extern __shared__ __align__(16) char smem[];
    const uint32_t sb = smem_u32(smem);

    const int tid  = threadIdx.x;
    const int mblk = blockIdx.y * 128;
    const int nblk = blockIdx.x * 128;
    const int w    = tid >> 5;
    const int l    = tid & 31;
    const int wm   = w & 3;        // 4 warps along M (32 rows each)
    const int wn   = w >> 2;       // 2 warps along N (64 cols each)
    const int g    = l >> 2;
    const int tig  = l & 3;

    // ldmatrix lane address offsets (bytes)
    const uint32_t laneA = (uint32_t)(((((l >> 3) & 1) * 8 + (l & 7)) * ROWB) + ((l >> 4) & 1) * 16);
    const uint32_t laneB = (uint32_t)(((((l >> 4) & 1) * 8 + (l & 7)) * ROWB) + ((l >> 3) & 1) * 16);

    float c[2][8][4];
#pragma unroll
    for (int m = 0; m < 2; m++)
#pragma unroll
        for (int n = 0; n < 8; n++)
#pragma unroll
            for (int k = 0; k < 4; k++) c[m][n][k] = 0.0f;

    // global row bases for the 4 tiles
    const __nv_bfloat16* gbase[4];
    gbase[0] = Ahi + (size_t)mblk * KD;
    gbase[1] = Alo + (size_t)mblk * KD;
    gbase[2] = Whi + (size_t)nblk * KD;
    gbase[3] = Wlo + (size_t)nblk * KD;

    // per-thread chunk-copy slots: 2048 16B units = [tile(4)][row(128)][ch(4)]
    int cpTile[8], cpRow[8], cpCh[8];
#pragma unroll
    for (int i = 0; i < 8; i++) {
        int idx  = tid + i * 256;
        cpTile[i] = idx >> 9;
        cpRow[i]  = (idx >> 2) & 127;
        cpCh[i]   = idx & 3;
    }

    const int nc = KD / 32;

    // issue chunk 0 into buffer 0
#pragma unroll
    for (int i = 0; i < 8; i++)
        cp16(sb + cpTile[i] * TILEB + cpRow[i] * ROWB + cpCh[i] * 16,
             gbase[cpTile[i]] + (size_t)cpRow[i] * KD + cpCh[i] * 8);
    asm volatile("cp.async.commit_group;" ::: "memory");

    for (int cc = 0; cc < nc; cc++) {
        if (cc + 1 < nc) {
            const int k0 = (cc + 1) * 32;
            const uint32_t bb = sb + ((cc + 1) & 1) * BUFB;
#pragma unroll
            for (int i = 0; i < 8; i++)
                cp16(bb + cpTile[i] * TILEB + cpRow[i] * ROWB + cpCh[i] * 16,
                     gbase[cpTile[i]] + (size_t)cpRow[i] * KD + k0 + cpCh[i] * 8);
            asm volatile("cp.async.commit_group;" ::: "memory");
            asm volatile("cp.async.wait_group 1;" ::: "memory");
        } else {
            asm volatile("cp.async.wait_group 0;" ::: "memory");
        }
        __syncthreads();

        const uint32_t bb  = sb + (cc & 1) * BUFB;
        const uint32_t aHi = bb + (uint32_t)(wm * 32) * ROWB + laneA;
        const uint32_t aLo = aHi + TILEB;
        const uint32_t wHi = bb + 2 * TILEB + (uint32_t)(wn * 64) * ROWB + laneB;
        const uint32_t wLo = wHi + TILEB;

#pragma unroll
        for (int ks = 0; ks < 2; ks++) {
            const uint32_t kb = ks * 32;       // 16 bf16 = 32 bytes
            uint32_t ah[2][4], al[2][4], bh[4][4], bl[4][4];
            ldm4(ah[0], aHi + kb);
            ldm4(ah[1], aHi + 16 * ROWB + kb);
            ldm4(al[0], aLo + kb);
            ldm4(al[1], aLo + 16 * ROWB + kb);
#pragma unroll
            for (int i = 0; i < 4; i++) {
                ldm4(bh[i], wHi + (uint32_t)(i * 16) * ROWB + kb);
                ldm4(bl[i], wLo + (uint32_t)(i * 16) * ROWB + kb);
            }
#pragma unroll
            for (int m = 0; m < 2; m++)
#pragma unroll
                for (int i = 0; i < 4; i++) {
                    mma_bf16(c[m][2 * i],     ah[m], &bh[i][0]);
                    mma_bf16(c[m][2 * i],     ah[m], &bl[i][0]);
                    mma_bf16(c[m][2 * i],     al[m], &bh[i][0]);
                    mma_bf16(c[m][2 * i + 1], ah[m], &bh[i][2]);
                    mma_bf16(c[m][2 * i + 1], ah[m], &bl[i][2]);
                    mma_bf16(c[m][2 * i + 1], al[m], &bh[i][2]);
                }
        }
        __syncthreads();
    }

    // ---- stage C through smem (reuse buffers; all tile reads are done) ----
    float* Cs   = (float*)smem;                 // [128][132]
    float* redS = Cs + 128 * 132;               // 256
    float* redQ = redS + 256;                   // 256
#pragma unroll
    for (int m = 0; m < 2; m++)
#pragma unroll
        for (int nb = 0; nb < 8; nb++) {
            const int row0 = wm * 32 + m * 16 + g;
            const int col0 = wn * 64 + nb * 8 + 2 * tig;
            *(float2*)&Cs[row0 * 132 + col0]       = make_float2(c[m][nb][0], c[m][nb][1]);
            *(float2*)&Cs[(row0 + 8) * 132 + col0] = make_float2(c[m][nb][2], c[m][nb][3]);
        }
    __syncthreads();

    // ---- epilogue: thread -> (row r, 64-col half) ----
    const int r    = tid >> 1;
    const int half = tid & 1;
    const int grow = mblk + r;
    const int n0   = nblk + half * 64;
    const float* crow = Cs + r * 132 + half * 64;

    if (EPI == 0) {
#pragma unroll
        for (int cidx = 0; cidx < 64; cidx += 4) {
            float4 v  = *(const float4*)(crow + cidx);
            float4 b4 = *(const float4*)(bias + n0 + cidx);
            float4 o;
            o.x = v.x + b4.x; o.y = v.y + b4.y; o.z = v.z + b4.z; o.w = v.w + b4.w;
            *(float4*)(outF + (size_t)grow * Nc + n0 + cidx) = o;
        }
    } else if (EPI == 1) {
#pragma unroll
        for (int c8 = 0; c8 < 64; c8 += 8) {
            __nv_bfloat16 hv[8], lv[8];
#pragma unroll
            for (int j = 0; j < 8; j++) {
                float v = gelu_tanh(crow[c8 + j] + bias[n0 + c8 + j]);
                split1(v, hv[j], lv[j]);
            }
            *(uint4*)(outHi + (size_t)grow * Nc + n0 + c8) = *(uint4*)hv;
            *(uint4*)(outLo + (size_t)grow * Nc + n0 + c8) = *(uint4*)lv;
        }
    } else {
        // bias + residual + LayerNorm over full 128-wide row (Nc==128, nblk==0)
        float vv[64];
        float s = 0.0f, q = 0.0f;
#pragma unroll
        for (int cidx = 0; cidx < 64; cidx += 4) {
            float4 v  = *(const float4*)(crow + cidx);
            float4 b4 = *(const float4*)(bias + n0 + cidx);
            float4 r4 = *(const float4*)(res + (size_t)grow * 128 + n0 + cidx);
            vv[cidx + 0] = v.x + b4.x + r4.x;
            vv[cidx + 1] = v.y + b4.y + r4.y;
            vv[cidx + 2] = v.z + b4.z + r4.z;
            vv[cidx + 3] = v.w + b4.w + r4.w;
#pragma unroll
            for (int j = 0; j < 4; j++) {
                s += vv[cidx + j];
                q = fmaf(vv[cidx + j], vv[cidx + j], q);
            }
        }
        redS[half * 128 + r] = s;
        redQ[half * 128 + r] = q;
        __syncthreads();
        const float ts = redS[r] + redS[128 + r];
        const float tq = redQ[r] + redQ[128 + r];
        const float mean = ts * (1.0f / 128.0f);
        const float var  = tq * (1.0f / 128.0f) - mean * mean;
        const float rstd = rsqrtf(var + 1e-5f);
#pragma unroll
        for (int c8 = 0; c8 < 64; c8 += 8) {
            float ov[8];
#pragma unroll
            for (int j = 0; j < 8; j++) {
                const int cidx = c8 + j;
                ov[j] = (vv[cidx] - mean) * rstd * gam[n0 + cidx] + bet[n0 + cidx];
            }
            *(float4*)(outF + (size_t)grow * 128 + n0 + c8)     = *(float4*)&ov[0];
            *(float4*)(outF + (size_t)grow * 128 + n0 + c8 + 4) = *(float4*)&ov[4];
            if (WSPLIT) {
                __nv_bfloat16 hv[8], lv[8];
#pragma unroll
                for (int j = 0; j < 8; j++) split1(ov[j], hv[j], lv[j]);
                *(uint4*)(outHi + (size_t)grow * 128 + n0 + c8) = *(uint4*)hv;
                *(uint4*)(outLo + (size_t)grow * 128 + n0 + c8) = *(uint4*)lv;
            }
        }
    }
}

// ---------------- convert fp32 -> bf16 hi/lo ----------------
__global__ __launch_bounds__(256) void convert_split_kernel(
    const float* __restrict__ in, __nv_bfloat16* __restrict__ hi,
    __nv_bfloat16* __restrict__ lo, int n4)
{
    int i = blockIdx.x * 256 + threadIdx.x;
    if (i < n4) {
        float4 v = ((const float4*)in)[i];
        __nv_bfloat16 h[4], l[4];
        split1(v.x, h[0], l[0]); split1(v.y, h[1], l[1]);
        split1(v.z, h[2], l[2]); split1(v.w, h[3], l[3]);
        ((uint2*)hi)[i] = *(uint2*)h;
        ((uint2*)lo)[i] = *(uint2*)l;
    }
}

// ---------------- temporal attention (scalar, split output) ----------------
__global__ __launch_bounds__(128) void temporal_attn_kernel(
    const float* __restrict__ qkv, __nv_bfloat16* __restrict__ ohi,
    __nv_bfloat16* __restrict__ olo)
{
    __shared__ __align__(16) float sq[Tdim][388];
    const int bn  = blockIdx.x;
    const int b   = bn / Ndim;
    const int n   = bn % Ndim;
    const int tid = threadIdx.x;

    for (int idx = tid; idx < Tdim * 96; idx += 128) {
        int t = idx / 96;
        int c = (idx % 96) * 4;
        size_t rr = ((size_t)(b * Tdim + t) * Ndim + n) * 384;
        *(float4*)&sq[t][c] = *(const float4*)(qkv + rr + c);
    }
    __syncthreads();

    if (tid < Hdim * Tdim) {
        const int h   = tid / Tdim;
        const int q   = tid % Tdim;
        const int off = h * 16;
        float qd[16];
#pragma unroll
        for (int d = 0; d < 16; d++) qd[d] = sq[q][off + d];
        float e[Tdim], Z = 0.0f;
#pragma unroll
        for (int s = 0; s < Tdim; s++) {
            float sc = 0.0f;
#pragma unroll
            for (int d = 0; d < 16; d++) sc = fmaf(qd[d], sq[s][128 + off + d], sc);
            e[s] = __expf(sc * 0.25f);
            Z += e[s];
        }
        float inv = 1.0f / Z;
        __nv_bfloat16 hv[16], lv[16];
#pragma unroll
        for (int d = 0; d < 16; d++) {
            float a = 0.0f;
#pragma unroll
            for (int s = 0; s < Tdim; s++) a = fmaf(e[s], sq[s][256 + off + d], a);
            split1(a * inv, hv[d], lv[d]);
        }
        size_t ro = ((size_t)(b * Tdim + q) * Ndim + n) * 128 + off;
        *(uint4*)(ohi + ro)     = *(uint4*)&hv[0];
        *(uint4*)(ohi + ro + 8) = *(uint4*)&hv[8];
        *(uint4*)(olo + ro)     = *(uint4*)&lv[0];
        *(uint4*)(olo + ro + 8) = *(uint4*)&lv[8];
    }
}

// ---------------- spatial attention (scalar, split output) ----------------
__global__ __launch_bounds__(352) void spatial_attn_kernel(
    const float* __restrict__ qkv, const float* __restrict__ gbias,
    __nv_bfloat16* __restrict__ ohi, __nv_bfloat16* __restrict__ olo)
{
    __shared__ __align__(16) float Ks[Ndim][16];
    __shared__ __align__(16) float Vs[Ndim][16];
    const int h   = blockIdx.x;
    const int bt  = blockIdx.y;
    const int tid = threadIdx.x;
    const size_t base = (size_t)bt * Ndim * 384;
    const int off = h * 16;

    for (int idx = tid; idx < Ndim * 4; idx += 352) {
        int j = idx >> 2;
        int c = (idx & 3) << 2;
        const float* p = qkv + base + (size_t)j * 384 + 128 + off + c;
        *(float4*)&Ks[j][c] = *(const float4*)p;
        *(float4*)&Vs[j][c] = *(const float4*)(p + 128);
    }
    __syncthreads();

    const int  q     = tid;
    const bool valid = (q < Ndim);
    const int  qc    = valid ? q : 0;

    float qr[16];
    const float* qp = qkv + base + (size_t)qc * 384 + off;
#pragma unroll
    for (int c = 0; c < 16; c += 4) {
        float4 v = *(const float4*)(qp + c);
        qr[c] = v.x; qr[c + 1] = v.y; qr[c + 2] = v.z; qr[c + 3] = v.w;
    }
    const float* brow = gbias + (size_t)qc * Ndim;

    float Z = 0.0f, acc[16];
#pragma unroll
    for (int d = 0; d < 16; d++) acc[d] = 0.0f;

    for (int j = 0; j < Ndim; j++) {
        const float4* kr = (const float4*)Ks[j];
        float s = 0.0f;
#pragma unroll
        for (int c = 0; c < 4; c++) {
            float4 kk = kr[c];
            s = fmaf(qr[c * 4 + 0], kk.x, s);
            s = fmaf(qr[c * 4 + 1], kk.y, s);
            s = fmaf(qr[c * 4 + 2], kk.z, s);
            s = fmaf(qr[c * 4 + 3], kk.w, s);
        }
        float e = __expf(fmaf(s, 0.25f, __ldg(brow + j)));
        Z += e;
        const float4* vr = (const float4*)Vs[j];
#pragma unroll
        for (int c = 0; c < 4; c++) {
            float4 vv = vr[c];
            acc[c * 4 + 0] = fmaf(e, vv.x, acc[c * 4 + 0]);
            acc[c * 4 + 1] = fmaf(e, vv.y, acc[c * 4 + 1]);
            acc[c * 4 + 2] = fmaf(e, vv.z, acc[c * 4 + 2]);
            acc[c * 4 + 3] = fmaf(e, vv.w, acc[c * 4 + 3]);
        }
    }

    if (valid) {
        float inv = 1.0f / Z;
        __nv_bfloat16 hv[16], lv[16];
#pragma unroll
        for (int d = 0; d < 16; d++) split1(acc[d] * inv, hv[d], lv[d]);
        size_t ro = ((size_t)bt * Ndim + q) * 128 + off;
        *(uint4*)(ohi + ro)     = *(uint4*)&hv[0];
        *(uint4*)(ohi + ro + 8) = *(uint4*)&hv[8];
        *(uint4*)(olo + ro)     = *(uint4*)&lv[0];
        *(uint4*)(olo + ro + 8) = *(uint4*)&lv[8];
    }
}

// ---------------- launch ----------------
extern "C" void kernel_launch(void* const* d_in, const int* in_sizes, int n_in,
                              void* d_out, int out_size)
{
    const float* x       = (const float*)d_in[0];
    const float* t_w_in  = (const float*)d_in[1];
    const float* t_b_in  = (const float*)d_in[2];
    const float* t_w_out = (const float*)d_in[3];
    const float* t_b_out = (const float*)d_in[4];
    const float* s_w_in  = (const float*)d_in[5];
    const float* s_b_in  = (const float*)d_in[6];
    const float* s_w_out = (const float*)d_in[7];
    const float* s_b_out = (const float*)d_in[8];
    const float* gbias   = (const float*)d_in[9];
    const float* ntg     = (const float*)d_in[10];
    const float* ntb     = (const float*)d_in[11];
    const float* nsg     = (const float*)d_in[12];
    const float* nsb     = (const float*)d_in[13];
    const float* ffw1    = (const float*)d_in[14];
    const float* ffb1    = (const float*)d_in[15];
    const float* ffw2    = (const float*)d_in[16];
    const float* ffb2    = (const float*)d_in[17];
    const float* nfg     = (const float*)d_in[18];
    const float* nfb     = (const float*)d_in[19];
    float* out = (float*)d_out;

    float *qkv, *x1f, *x2f;
    __nv_bfloat16 *xhi, *xlo, *ahi, *alo, *bhi, *blo, *hhi, *hlo, *whi, *wlo;
    cudaGetSymbolAddress((void**)&qkv, g_qkv);
    cudaGetSymbolAddress((void**)&x1f, g_x1f);
    cudaGetSymbolAddress((void**)&x2f, g_x2f);
    cudaGetSymbolAddress((void**)&xhi, g_xhi);
    cudaGetSymbolAddress((void**)&xlo, g_xlo);
    cudaGetSymbolAddress((void**)&ahi, g_ahi);
    cudaGetSymbolAddress((void**)&alo, g_alo);
    cudaGetSymbolAddress((void**)&bhi, g_bhi);
    cudaGetSymbolAddress((void**)&blo, g_blo);
    cudaGetSymbolAddress((void**)&hhi, g_hhi);
    cudaGetSymbolAddress((void**)&hlo, g_hlo);
    cudaGetSymbolAddress((void**)&whi, g_whi);
    cudaGetSymbolAddress((void**)&wlo, g_wlo);

    cudaFuncSetAttribute(mm_kernel<128, 0, false>, cudaFuncAttributeMaxDynamicSharedMemorySize, SMEM_DYN);
    cudaFuncSetAttribute(mm_kernel<128, 1, false>, cudaFuncAttributeMaxDynamicSharedMemorySize, SMEM_DYN);
    cudaFuncSetAttribute(mm_kernel<128, 2, true >, cudaFuncAttributeMaxDynamicSharedMemorySize, SMEM_DYN);
    cudaFuncSetAttribute(mm_kernel<512, 2, false>, cudaFuncAttributeMaxDynamicSharedMemorySize, SMEM_DYN);

    // converts: x + all weights
    convert_split_kernel<<<(BTN * 128 / 4 + 255) / 256, 256>>>(x, xhi, xlo, BTN * 128 / 4);
    convert_split_kernel<<<48, 256>>>(t_w_in,  whi + WOFF_TIN,  wlo + WOFF_TIN,  49152 / 4);
    convert_split_kernel<<<48, 256>>>(s_w_in,  whi + WOFF_SIN,  wlo + WOFF_SIN,  49152 / 4);
    convert_split_kernel<<<16, 256>>>(t_w_out, whi + WOFF_TOUT, wlo + WOFF_TOUT, 16384 / 4);
    convert_split_kernel<<<16, 256>>>(s_w_out, whi + WOFF_SOUT, wlo + WOFF_SOUT, 16384 / 4);
    convert_split_kernel<<<64, 256>>>(ffw1,    whi + WOFF_FF1,  wlo + WOFF_FF1,  65536 / 4);
    convert_split_kernel<<<64, 256>>>(ffw2,    whi + WOFF_FF2,  wlo + WOFF_FF2,  65536 / 4);

    // 1) temporal QKV
    mm_kernel<128, 0, false><<<dim3(3, MTILES), 256, SMEM_DYN>>>(
        xhi, xlo, whi + WOFF_TIN, wlo + WOFF_TIN, t_b_in,
        nullptr, nullptr, nullptr, qkv, nullptr, nullptr, 384);
    // 2) temporal attention -> split
    temporal_attn_kernel<<<BNSEQ, 128>>>(qkv, ahi, alo);
    // 3) temporal out-proj + res + LN -> x1 fp32 + split (bhi/blo)
    mm_kernel<128, 2, true><<<dim3(1, MTILES), 256, SMEM_DYN>>>(
        ahi, alo, whi + WOFF_TOUT, wlo + WOFF_TOUT, t_b_out,
        x, ntg, ntb, x1f, bhi, blo, 128);
    // 4) spatial QKV
    mm_kernel<128, 0, false><<<dim3(3, MTILES), 256, SMEM_DYN>>>(
        bhi, blo, whi + WOFF_SIN, wlo + WOFF_SIN, s_b_in,
        nullptr, nullptr, nullptr, qkv, nullptr, nullptr, 384);
    // 5) spatial attention -> split
    spatial_attn_kernel<<<dim3(Hdim, BTSEQ), 352>>>(qkv, gbias, ahi, alo);
    // 6) spatial out-proj + res + LN -> x2 fp32 + split (reuse xhi/xlo)
    mm_kernel<128, 2, true><<<dim3(1, MTILES), 256, SMEM_DYN>>>(
        ahi, alo, whi + WOFF_SOUT, wlo + WOFF_SOUT, s_b_out,
        x1f, nsg, nsb, x2f, xhi, xlo, 128);
    // 7) FFN up + GELU -> split hbuf
    mm_kernel<128, 1, false><<<dim3(4, MTILES), 256, SMEM_DYN>>>(
        xhi, xlo, whi + WOFF_FF1, wlo + WOFF_FF1, ffb1,
        nullptr, nullptr, nullptr, nullptr, hhi, hlo, 512);
    // 8) FFN down + res + LN -> final output
    mm_kernel<512, 2, false><<<dim3(1, MTILES), 256, SMEM_DYN>>>(
        hhi, hlo, whi + WOFF_FF2, wlo + WOFF_FF2, ffb2,
        x2f, nfg, nfb, out, nullptr, nullptr, 128);
}

// round 12
// speedup vs baseline: 1.3372x; 1.0142x over previous
#include <cuda_runtime.h>
#include <cuda_bf16.h>
#include <math.h>
#include <stddef.h>
#include <stdint.h>

// ---------------- problem constants ----------------
#define Bdim 32
#define Tdim 12
#define Ndim 325
#define Ddim 128
#define Hdim 8
#define Fdim 512
#define BTN  124800          // B*T*N tokens
#define BNSEQ 10400          // B*N temporal sequences
#define BTSEQ 384            // B*T spatial sequences
#define MTILES 975           // BTN / 128

// ---------------- scratch (no-alloc rule: __device__ globals) ----------------
static __device__ float g_qkv[(size_t)BTN * 384];
static __device__ float g_x1f[(size_t)BTN * 128];
static __device__ float g_x2f[(size_t)BTN * 128];
static __device__ __nv_bfloat16 g_xhi[(size_t)BTN * 128];
static __device__ __nv_bfloat16 g_xlo[(size_t)BTN * 128];
static __device__ __nv_bfloat16 g_ahi[(size_t)BTN * 128];
static __device__ __nv_bfloat16 g_alo[(size_t)BTN * 128];
static __device__ __nv_bfloat16 g_bhi[(size_t)BTN * 128];
static __device__ __nv_bfloat16 g_blo[(size_t)BTN * 128];
static __device__ __nv_bfloat16 g_hhi[(size_t)BTN * 512];
static __device__ __nv_bfloat16 g_hlo[(size_t)BTN * 512];
static __device__ __nv_bfloat16 g_whi[262144];
static __device__ __nv_bfloat16 g_wlo[262144];
// weight offsets inside g_whi/g_wlo (elements)
#define WOFF_TIN  0
#define WOFF_SIN  49152
#define WOFF_TOUT 98304
#define WOFF_SOUT 114688
#define WOFF_FF1  131072
#define WOFF_FF2  196608

// ---------------- helpers ----------------
__device__ __forceinline__ uint32_t smem_u32(const void* p) {
    uint32_t a;
    asm("{ .reg .u64 t; cvta.to.shared.u64 t, %1; cvt.u32.u64 %0, t; }" : "=r"(a) : "l"(p));
    return a;
}
__device__ __forceinline__ void split1(float x, __nv_bfloat16& h, __nv_bfloat16& l) {
    h = __float2bfloat16(x);
    l = __float2bfloat16(x - __bfloat162float(h));
}
__device__ __forceinline__ float gelu_tanh(float v) {
    float c = 0.7978845608028654f * (v + 0.044715f * v * v * v);
    return 0.5f * v * (1.0f + tanhf(c));
}
__device__ __forceinline__ void ldm4(uint32_t* r, uint32_t addr) {
    asm volatile("ldmatrix.sync.aligned.m8n8.x4.shared.b16 {%0,%1,%2,%3}, [%4];"
                 : "=r"(r[0]), "=r"(r[1]), "=r"(r[2]), "=r"(r[3]) : "r"(addr));
}
__device__ __forceinline__ void mma_bf16(float* c, const uint32_t* a, const uint32_t* b) {
    asm volatile(
        "mma.sync.aligned.m16n8k16.row.col.f32.bf16.bf16.f32 "
        "{%0,%1,%2,%3}, {%4,%5,%6,%7}, {%8,%9}, {%0,%1,%2,%3};"
        : "+f"(c[0]), "+f"(c[1]), "+f"(c[2]), "+f"(c[3])
        : "r"(a[0]), "r"(a[1]), "r"(a[2]), "r"(a[3]), "r"(b[0]), "r"(b[1]));
}
__device__ __forceinline__ void cp16(uint32_t s, const void* g) {
    asm volatile("cp.async.cg.shared.global [%0], [%1], 16;" :: "r"(s), "l"(g));
}
__device__ __forceinline__ uint32_t pkbf(__nv_bfloat16 a, __nv_bfloat16 b) {
    return ((uint32_t)__bfloat16_as_ushort(b) << 16) | (uint32_t)__bfloat16_as_ushort(a);
}

// ---------------- split-bf16 HMMA GEMM (validated R11) ----------------
#define ROWB   80
#define TILEB  10240
#define BUFB   40960
#define SMEM_DYN 81920

template <int KD, int EPI, bool WSPLIT>
__global__ __launch_bounds__(256) void mm_kernel(
    const __nv_bfloat16* __restrict__ Ahi, const __nv_bfloat16* __restrict__ Alo,
    const __nv_bfloat16* __restrict__ Whi, const __nv_bfloat16* __restrict__ Wlo,
    const float* __restrict__ bias,
    const float* __restrict__ res, const float* __restrict__ gam, const float* __restrict__ bet,
    float* __restrict__ outF, __nv_bfloat16* __restrict__ outHi, __nv_bfloat16* __restrict__ outLo,
    int Nc)
{
    extern __shared__ __align__(16) char smem[];
    const uint32_t sb = smem_u32(smem);

    const int tid  = threadIdx.x;
    const int mblk = blockIdx.y * 128;
    const int nblk = blockIdx.x * 128;
    const int w    = tid >> 5;
    const int l    = tid & 31;
    const int wm   = w & 3;
    const int wn   = w >> 2;
    const int g    = l >> 2;
    const int tig  = l & 3;

    const uint32_t laneA = (uint32_t)(((((l >> 3) & 1) * 8 + (l & 7)) * ROWB) + ((l >> 4) & 1) * 16);
    const uint32_t laneB = (uint32_t)(((((l >> 4) & 1) * 8 + (l & 7)) * ROWB) + ((l >> 3) & 1) * 16);

    float c[2][8][4];
#pragma unroll
    for (int m = 0; m < 2; m++)
#pragma unroll
        for (int n = 0; n < 8; n++)
#pragma unroll
            for (int k = 0; k < 4; k++) c[m][n][k] = 0.0f;

    const __nv_bfloat16* gbase[4];
    gbase[0] = Ahi + (size_t)mblk * KD;
    gbase[1] = Alo + (size_t)mblk * KD;
    gbase[2] = Whi + (size_t)nblk * KD;
    gbase[3] = Wlo + (size_t)nblk * KD;

    int cpTile[8], cpRow[8], cpCh[8];
#pragma unroll
    for (int i = 0; i < 8; i++) {
        int idx  = tid + i * 256;
        cpTile[i] = idx >> 9;
        cpRow[i]  = (idx >> 2) & 127;
        cpCh[i]   = idx & 3;
    }

    const int nc = KD / 32;

#pragma unroll
    for (int i = 0; i < 8; i++)
        cp16(sb + cpTile[i] * TILEB + cpRow[i] * ROWB + cpCh[i] * 16,
             gbase[cpTile[i]] + (size_t)cpRow[i] * KD + cpCh[i] * 8);
    asm volatile("cp.async.commit_group;" ::: "memory");

    for (int cc = 0; cc < nc; cc++) {
        if (cc + 1 < nc) {
            const int k0 = (cc + 1) * 32;
            const uint32_t bb = sb + ((cc + 1) & 1) * BUFB;
#pragma unroll
            for (int i = 0; i < 8; i++)
                cp16(bb + cpTile[i] * TILEB + cpRow[i] * ROWB + cpCh[i] * 16,
                     gbase[cpTile[i]] + (size_t)cpRow[i] * KD + k0 + cpCh[i] * 8);
            asm volatile("cp.async.commit_group;" ::: "memory");
            asm volatile("cp.async.wait_group 1;" ::: "memory");
        } else {
            asm volatile("cp.async.wait_group 0;" ::: "memory");
        }
        __syncthreads();

        const uint32_t bb  = sb + (cc & 1) * BUFB;
        const uint32_t aHi = bb + (uint32_t)(wm * 32) * ROWB + laneA;
        const uint32_t aLo = aHi + TILEB;
        const uint32_t wHi = bb + 2 * TILEB + (uint32_t)(wn * 64) * ROWB + laneB;
        const uint32_t wLo = wHi + TILEB;

#pragma unroll
        for (int ks = 0; ks < 2; ks++) {
            const uint32_t kb = ks * 32;
            uint32_t ah[2][4], al[2][4], bh[4][4], bl[4][4];
            ldm4(ah[0], aHi + kb);
            ldm4(ah[1], aHi + 16 * ROWB + kb);
            ldm4(al[0], aLo + kb);
            ldm4(al[1], aLo + 16 * ROWB + kb);
#pragma unroll
            for (int i = 0; i < 4; i++) {
                ldm4(bh[i], wHi + (uint32_t)(i * 16) * ROWB + kb);
                ldm4(bl[i], wLo + (uint32_t)(i * 16) * ROWB + kb);
            }
#pragma unroll
            for (int m = 0; m < 2; m++)
#pragma unroll
                for (int i = 0; i < 4; i++) {
                    mma_bf16(c[m][2 * i],     ah[m], &bh[i][0]);
                    mma_bf16(c[m][2 * i],     ah[m], &bl[i][0]);
                    mma_bf16(c[m][2 * i],     al[m], &bh[i][0]);
                    mma_bf16(c[m][2 * i + 1], ah[m], &bh[i][2]);
                    mma_bf16(c[m][2 * i + 1], ah[m], &bl[i][2]);
                    mma_bf16(c[m][2 * i + 1], al[m], &bh[i][2]);
                }
        }
        __syncthreads();
    }

    float* Cs   = (float*)smem;
    float* redS = Cs + 128 * 132;
    float* redQ = redS + 256;
#pragma unroll
    for (int m = 0; m < 2; m++)
#pragma unroll
        for (int nb = 0; nb < 8; nb++) {
            const int row0 = wm * 32 + m * 16 + g;
            const int col0 = wn * 64 + nb * 8 + 2 * tig;
            *(float2*)&Cs[row0 * 132 + col0]       = make_float2(c[m][nb][0], c[m][nb][1]);
            *(float2*)&Cs[(row0 + 8) * 132 + col0] = make_float2(c[m][nb][2], c[m][nb][3]);
        }
    __syncthreads();

    const int r    = tid >> 1;
    const int half = tid & 1;
    const int grow = mblk + r;
    const int n0   = nblk + half * 64;
    const float* crow = Cs + r * 132 + half * 64;

    if (EPI == 0) {
#pragma unroll
        for (int cidx = 0; cidx < 64; cidx += 4) {
            float4 v  = *(const float4*)(crow + cidx);
            float4 b4 = *(const float4*)(bias + n0 + cidx);
            float4 o;
            o.x = v.x + b4.x; o.y = v.y + b4.y; o.z = v.z + b4.z; o.w = v.w + b4.w;
            *(float4*)(outF + (size_t)grow * Nc + n0 + cidx) = o;
        }
    } else if (EPI == 1) {
#pragma unroll
        for (int c8 = 0; c8 < 64; c8 += 8) {
            __nv_bfloat16 hv[8], lv[8];
#pragma unroll
            for (int j = 0; j < 8; j++) {
                float v = gelu_tanh(crow[c8 + j] + bias[n0 + c8 + j]);
                split1(v, hv[j], lv[j]);
            }
            *(uint4*)(outHi + (size_t)grow * Nc + n0 + c8) = *(uint4*)hv;
            *(uint4*)(outLo + (size_t)grow * Nc + n0 + c8) = *(uint4*)lv;
        }
    } else {
        float vv[64];
        float s = 0.0f, q = 0.0f;
#pragma unroll
        for (int cidx = 0; cidx < 64; cidx += 4) {
            float4 v  = *(const float4*)(crow + cidx);
            float4 b4 = *(const float4*)(bias + n0 + cidx);
            float4 r4 = *(const float4*)(res + (size_t)grow * 128 + n0 + cidx);
            vv[cidx + 0] = v.x + b4.x + r4.x;
            vv[cidx + 1] = v.y + b4.y + r4.y;
            vv[cidx + 2] = v.z + b4.z + r4.z;
            vv[cidx + 3] = v.w + b4.w + r4.w;
#pragma unroll
            for (int j = 0; j < 4; j++) {
                s += vv[cidx + j];
                q = fmaf(vv[cidx + j], vv[cidx + j], q);
            }
        }
        redS[half * 128 + r] = s;
        redQ[half * 128 + r] = q;
        __syncthreads();
        const float ts = redS[r] + redS[128 + r];
        const float tq = redQ[r] + redQ[128 + r];
        const float mean = ts * (1.0f / 128.0f);
        const float var  = tq * (1.0f / 128.0f) - mean * mean;
        const float rstd = rsqrtf(var + 1e-5f);
#pragma unroll
        for (int c8 = 0; c8 < 64; c8 += 8) {
            float ov[8];
#pragma unroll
            for (int j = 0; j < 8; j++) {
                const int cidx = c8 + j;
                ov[j] = (vv[cidx] - mean) * rstd * gam[n0 + cidx] + bet[n0 + cidx];
            }
            *(float4*)(outF + (size_t)grow * 128 + n0 + c8)     = *(float4*)&ov[0];
            *(float4*)(outF + (size_t)grow * 128 + n0 + c8 + 4) = *(float4*)&ov[4];
            if (WSPLIT) {
                __nv_bfloat16 hv[8], lv[8];
#pragma unroll
                for (int j = 0; j < 8; j++) split1(ov[j], hv[j], lv[j]);
                *(uint4*)(outHi + (size_t)grow * 128 + n0 + c8) = *(uint4*)hv;
                *(uint4*)(outLo + (size_t)grow * 128 + n0 + c8) = *(uint4*)lv;
            }
        }
    }
}

// ---------------- convert fp32 -> bf16 hi/lo ----------------
__global__ __launch_bounds__(256) void convert_split_kernel(
    const float* __restrict__ in, __nv_bfloat16* __restrict__ hi,
    __nv_bfloat16* __restrict__ lo, int n4)
{
    int i = blockIdx.x * 256 + threadIdx.x;
    if (i < n4) {
        float4 v = ((const float4*)in)[i];
        __nv_bfloat16 h[4], l[4];
        split1(v.x, h[0], l[0]); split1(v.y, h[1], l[1]);
        split1(v.z, h[2], l[2]); split1(v.w, h[3], l[3]);
        ((uint2*)hi)[i] = *(uint2*)h;
        ((uint2*)lo)[i] = *(uint2*)l;
    }
}

// ---------------- temporal attention (scalar, split output) ----------------
__global__ __launch_bounds__(128) void temporal_attn_kernel(
    const float* __restrict__ qkv, __nv_bfloat16* __restrict__ ohi,
    __nv_bfloat16* __restrict__ olo)
{
    __shared__ __align__(16) float sq[Tdim][388];
    const int bn  = blockIdx.x;
    const int b   = bn / Ndim;
    const int n   = bn % Ndim;
    const int tid = threadIdx.x;

    for (int idx = tid; idx < Tdim * 96; idx += 128) {
        int t = idx / 96;
        int c = (idx % 96) * 4;
        size_t rr = ((size_t)(b * Tdim + t) * Ndim + n) * 384;
        *(float4*)&sq[t][c] = *(const float4*)(qkv + rr + c);
    }
    __syncthreads();

    if (tid < Hdim * Tdim) {
        const int h   = tid / Tdim;
        const int q   = tid % Tdim;
        const int off = h * 16;
        float qd[16];
#pragma unroll
        for (int d = 0; d < 16; d++) qd[d] = sq[q][off + d];
        float e[Tdim], Z = 0.0f;
#pragma unroll
        for (int s = 0; s < Tdim; s++) {
            float sc = 0.0f;
#pragma unroll
            for (int d = 0; d < 16; d++) sc = fmaf(qd[d], sq[s][128 + off + d], sc);
            e[s] = __expf(sc * 0.25f);
            Z += e[s];
        }
        float inv = 1.0f / Z;
        __nv_bfloat16 hv[16], lv[16];
#pragma unroll
        for (int d = 0; d < 16; d++) {
            float a = 0.0f;
#pragma unroll
            for (int s = 0; s < Tdim; s++) a = fmaf(e[s], sq[s][256 + off + d], a);
            split1(a * inv, hv[d], lv[d]);
        }
        size_t ro = ((size_t)(b * Tdim + q) * Ndim + n) * 128 + off;
        *(uint4*)(ohi + ro)     = *(uint4*)&hv[0];
        *(uint4*)(ohi + ro + 8) = *(uint4*)&hv[8];
        *(uint4*)(olo + ro)     = *(uint4*)&lv[0];
        *(uint4*)(olo + ro + 8) = *(uint4*)&lv[8];
    }
}

// ---------------- spatial attention: HMMA flash-style (no-max softmax) ----------------
// block = (head, bt, 128-query tile). smem (bytes):
//   QHI 0 (6144) QLO 6144 | KHI 12288 (18432) KLO 30720 | VTHI 49152 (12544) VTLO 61696
//   BIAS 74240 (128 x 66 fp32 = 33792)  total 108032
#define SA_SMEM 108032

__global__ __launch_bounds__(256) void spatial_attn_mma_kernel(
    const float* __restrict__ qkv, const float* __restrict__ gbias,
    __nv_bfloat16* __restrict__ ohi, __nv_bfloat16* __restrict__ olo)
{
    extern __shared__ __align__(16) char smem[];
    __nv_bfloat16* sp = (__nv_bfloat16*)smem;
    float* bs = (float*)(smem + 74240);
    const uint32_t sb = smem_u32(smem);

    const int h   = blockIdx.x;
    const int bt  = blockIdx.y;
    const int q0  = blockIdx.z * 128;
    const int tid = threadIdx.x;
    const int w   = tid >> 5, l = tid & 31;
    const int g   = l >> 2, tig = l & 3;
    const size_t base = (size_t)bt * Ndim * 384;

    // ---- load + split Q (128x16), K (384x16, zero-pad), Vt (16x384, zero-pad) ----
    for (int e = tid; e < 2048; e += 256) {
        int row = e >> 4, d = e & 15;
        float v = (q0 + row < Ndim) ? qkv[base + (size_t)(q0 + row) * 384 + h * 16 + d] : 0.f;
        __nv_bfloat16 hb, lb; split1(v, hb, lb);
        sp[row * 24 + d] = hb; sp[3072 + row * 24 + d] = lb;
    }
    for (int e = tid; e < 6144; e += 256) {
        int row = e >> 4, d = e & 15;
        float kv = (row < Ndim) ? qkv[base + (size_t)row * 384 + 128 + h * 16 + d] : 0.f;
        __nv_bfloat16 hb, lb; split1(kv, hb, lb);
        sp[6144 + row * 24 + d] = hb; sp[15360 + row * 24 + d] = lb;
        float vv = (row < Ndim) ? qkv[base + (size_t)row * 384 + 256 + h * 16 + d] : 0.f;
        split1(vv, hb, lb);
        sp[24576 + d * 392 + row] = hb; sp[30848 + d * 392 + row] = lb;
    }
    __syncthreads();

    const uint32_t laneA = (uint32_t)((((l >> 3) & 1) * 8 + (l & 7)) * 48 + ((l >> 4) & 1) * 16);
    const uint32_t laneB = (uint32_t)((((l >> 4) & 1) * 8 + (l & 7)) * 48 + ((l >> 3) & 1) * 16);
    const uint32_t laneV = (uint32_t)((((l >> 4) & 1) * 8 + (l & 7)) * 784 + ((l >> 3) & 1) * 16);

    // Q fragments (persist across key chunks)
    uint32_t qh4[4], ql4[4];
    ldm4(qh4, sb + 0    + (uint32_t)(w * 16) * 48 + laneA);
    ldm4(ql4, sb + 6144 + (uint32_t)(w * 16) * 48 + laneA);

    float o0[4] = {0.f, 0.f, 0.f, 0.f}, o1[4] = {0.f, 0.f, 0.f, 0.f};
    float zg = 0.f, zh = 0.f;
    const int r0 = w * 16 + g, r1 = r0 + 8;

    for (int ch = 0; ch < 6; ch++) {
        __syncthreads();
        // stage bias chunk (coalesced)
        for (int e = tid; e < 8192; e += 256) {
            int row = e >> 6, col = e & 63;
            int qq = q0 + row, jj = ch * 64 + col;
            bs[row * 66 + col] = (qq < Ndim && jj < Ndim) ? gbias[qq * Ndim + jj] : 0.f;
        }
        __syncthreads();

        // scores: 8 n8 tiles, 3-product split
        float s[8][4];
#pragma unroll
        for (int t = 0; t < 8; t++)
#pragma unroll
            for (int k = 0; k < 4; k++) s[t][k] = 0.f;
#pragma unroll
        for (int i = 0; i < 4; i++) {
            uint32_t kh[4], kl[4];
            ldm4(kh, sb + 12288 + (uint32_t)(ch * 64 + i * 16) * 48 + laneB);
            ldm4(kl, sb + 30720 + (uint32_t)(ch * 64 + i * 16) * 48 + laneB);
            mma_bf16(s[2 * i],     qh4, &kh[0]);
            mma_bf16(s[2 * i],     qh4, &kl[0]);
            mma_bf16(s[2 * i],     ql4, &kh[0]);
            mma_bf16(s[2 * i + 1], qh4, &kh[2]);
            mma_bf16(s[2 * i + 1], qh4, &kl[2]);
            mma_bf16(s[2 * i + 1], ql4, &kh[2]);
        }

        // softmax numerators -> P fragments (hi/lo)
        uint32_t pah[4][4], pal[4][4];
#pragma unroll
        for (int t = 0; t < 8; t++) {
            const int f = t >> 1, hf = t & 1;
            const int jl = f * 16 + hf * 8 + 2 * tig;
            const int jglob = ch * 64 + jl;
            float p0 = (jglob     < Ndim) ? __expf(fmaf(s[t][0], 0.25f, bs[r0 * 66 + jl]))     : 0.f;
            float p1 = (jglob + 1 < Ndim) ? __expf(fmaf(s[t][1], 0.25f, bs[r0 * 66 + jl + 1])) : 0.f;
            float p2 = (jglob     < Ndim) ? __expf(fmaf(s[t][2], 0.25f, bs[r1 * 66 + jl]))     : 0.f;
            float p3 = (jglob + 1 < Ndim) ? __expf(fmaf(s[t][3], 0.25f, bs[r1 * 66 + jl + 1])) : 0.f;
            zg += p0 + p1; zh += p2 + p3;
            __nv_bfloat16 h0, l0, h1, l1, h2, l2, h3, l3;
            split1(p0, h0, l0); split1(p1, h1, l1);
            split1(p2, h2, l2); split1(p3, h3, l3);
            pah[f][hf * 2 + 0] = pkbf(h0, h1);
            pah[f][hf * 2 + 1] = pkbf(h2, h3);
            pal[f][hf * 2 + 0] = pkbf(l0, l1);
            pal[f][hf * 2 + 1] = pkbf(l2, l3);
        }

        // P @ V (3-product split)
#pragma unroll
        for (int kf = 0; kf < 4; kf++) {
            uint32_t vh[4], vl[4];
            ldm4(vh, sb + 49152 + laneV + (uint32_t)(ch * 64 + kf * 16) * 2);
            ldm4(vl, sb + 61696 + laneV + (uint32_t)(ch * 64 + kf * 16) * 2);
            mma_bf16(o0, pah[kf], &vh[0]);
            mma_bf16(o0, pah[kf], &vl[0]);
            mma_bf16(o0, pal[kf], &vh[0]);
            mma_bf16(o1, pah[kf], &vh[2]);
            mma_bf16(o1, pah[kf], &vl[2]);
            mma_bf16(o1, pal[kf], &vh[2]);
        }
    }

    // finish Z (quad reduce) and write split-bf16 outputs
    zg += __shfl_xor_sync(0xffffffffu, zg, 1);
    zg += __shfl_xor_sync(0xffffffffu, zg, 2);
    zh += __shfl_xor_sync(0xffffffffu, zh, 1);
    zh += __shfl_xor_sync(0xffffffffu, zh, 2);
    const float ig = 1.f / zg, ih = 1.f / zh;

    const int qg = q0 + r0;
    if (qg < Ndim) {
        size_t rb = ((size_t)bt * Ndim + qg) * 128 + h * 16;
        __nv_bfloat16 ha, la, hb2, lb2;
        split1(o0[0] * ig, ha, la); split1(o0[1] * ig, hb2, lb2);
        *(uint32_t*)(ohi + rb + 2 * tig) = pkbf(ha, hb2);
        *(uint32_t*)(olo + rb + 2 * tig) = pkbf(la, lb2);
        split1(o1[0] * ig, ha, la); split1(o1[1] * ig, hb2, lb2);
        *(uint32_t*)(ohi + rb + 8 + 2 * tig) = pkbf(ha, hb2);
        *(uint32_t*)(olo + rb + 8 + 2 * tig) = pkbf(la, lb2);
    }
    const int qh8 = q0 + r1;
    if (qh8 < Ndim) {
        size_t rb = ((size_t)bt * Ndim + qh8) * 128 + h * 16;
        __nv_bfloat16 ha, la, hb2, lb2;
        split1(o0[2] * ih, ha, la); split1(o0[3] * ih, hb2, lb2);
        *(uint32_t*)(ohi + rb + 2 * tig) = pkbf(ha, hb2);
        *(uint32_t*)(olo + rb + 2 * tig) = pkbf(la, lb2);
        split1(o1[2] * ih, ha, la); split1(o1[3] * ih, hb2, lb2);
        *(uint32_t*)(ohi + rb + 8 + 2 * tig) = pkbf(ha, hb2);
        *(uint32_t*)(olo + rb + 8 + 2 * tig) = pkbf(la, lb2);
    }
}

// ---------------- launch ----------------
extern "C" void kernel_launch(void* const* d_in, const int* in_sizes, int n_in,
                              void* d_out, int out_size)
{
    const float* x       = (const float*)d_in[0];
    const float* t_w_in  = (const float*)d_in[1];
    const float* t_b_in  = (const float*)d_in[2];
    const float* t_w_out = (const float*)d_in[3];
    const float* t_b_out = (const float*)d_in[4];
    const float* s_w_in  = (const float*)d_in[5];
    const float* s_b_in  = (const float*)d_in[6];
    const float* s_w_out = (const float*)d_in[7];
    const float* s_b_out = (const float*)d_in[8];
    const float* gbias   = (const float*)d_in[9];
    const float* ntg     = (const float*)d_in[10];
    const float* ntb     = (const float*)d_in[11];
    const float* nsg     = (const float*)d_in[12];
    const float* nsb     = (const float*)d_in[13];
    const float* ffw1    = (const float*)d_in[14];
    const float* ffb1    = (const float*)d_in[15];
    const float* ffw2    = (const float*)d_in[16];
    const float* ffb2    = (const float*)d_in[17];
    const float* nfg     = (const float*)d_in[18];
    const float* nfb     = (const float*)d_in[19];
    float* out = (float*)d_out;

    float *qkv, *x1f, *x2f;
    __nv_bfloat16 *xhi, *xlo, *ahi, *alo, *bhi, *blo, *hhi, *hlo, *whi, *wlo;
    cudaGetSymbolAddress((void**)&qkv, g_qkv);
    cudaGetSymbolAddress((void**)&x1f, g_x1f);
    cudaGetSymbolAddress((void**)&x2f, g_x2f);
    cudaGetSymbolAddress((void**)&xhi, g_xhi);
    cudaGetSymbolAddress((void**)&xlo, g_xlo);
    cudaGetSymbolAddress((void**)&ahi, g_ahi);
    cudaGetSymbolAddress((void**)&alo, g_alo);
    cudaGetSymbolAddress((void**)&bhi, g_bhi);
    cudaGetSymbolAddress((void**)&blo, g_blo);
    cudaGetSymbolAddress((void**)&hhi, g_hhi);
    cudaGetSymbolAddress((void**)&hlo, g_hlo);
    cudaGetSymbolAddress((void**)&whi, g_whi);
    cudaGetSymbolAddress((void**)&wlo, g_wlo);

    cudaFuncSetAttribute(mm_kernel<128, 0, false>, cudaFuncAttributeMaxDynamicSharedMemorySize, SMEM_DYN);
    cudaFuncSetAttribute(mm_kernel<128, 1, false>, cudaFuncAttributeMaxDynamicSharedMemorySize, SMEM_DYN);
    cudaFuncSetAttribute(mm_kernel<128, 2, true >, cudaFuncAttributeMaxDynamicSharedMemorySize, SMEM_DYN);
    cudaFuncSetAttribute(mm_kernel<512, 2, false>, cudaFuncAttributeMaxDynamicSharedMemorySize, SMEM_DYN);
    cudaFuncSetAttribute(spatial_attn_mma_kernel, cudaFuncAttributeMaxDynamicSharedMemorySize, SA_SMEM);

    // converts: x + all weights
    convert_split_kernel<<<(BTN * 128 / 4 + 255) / 256, 256>>>(x, xhi, xlo, BTN * 128 / 4);
    convert_split_kernel<<<48, 256>>>(t_w_in,  whi + WOFF_TIN,  wlo + WOFF_TIN,  49152 / 4);
    convert_split_kernel<<<48, 256>>>(s_w_in,  whi + WOFF_SIN,  wlo + WOFF_SIN,  49152 / 4);
    convert_split_kernel<<<16, 256>>>(t_w_out, whi + WOFF_TOUT, wlo + WOFF_TOUT, 16384 / 4);
    convert_split_kernel<<<16, 256>>>(s_w_out, whi + WOFF_SOUT, wlo + WOFF_SOUT, 16384 / 4);
    convert_split_kernel<<<64, 256>>>(ffw1,    whi + WOFF_FF1,  wlo + WOFF_FF1,  65536 / 4);
    convert_split_kernel<<<64, 256>>>(ffw2,    whi + WOFF_FF2,  wlo + WOFF_FF2,  65536 / 4);

    // 1) temporal QKV
    mm_kernel<128, 0, false><<<dim3(3, MTILES), 256, SMEM_DYN>>>(
        xhi, xlo, whi + WOFF_TIN, wlo + WOFF_TIN, t_b_in,
        nullptr, nullptr, nullptr, qkv, nullptr, nullptr, 384);
    // 2) temporal attention -> split
    temporal_attn_kernel<<<BNSEQ, 128>>>(qkv, ahi, alo);
    // 3) temporal out-proj + res + LN -> x1 fp32 + split (bhi/blo)
    mm_kernel<128, 2, true><<<dim3(1, MTILES), 256, SMEM_DYN>>>(
        ahi, alo, whi + WOFF_TOUT, wlo + WOFF_TOUT, t_b_out,
        x, ntg, ntb, x1f, bhi, blo, 128);
    // 4) spatial QKV
    mm_kernel<128, 0, false><<<dim3(3, MTILES), 256, SMEM_DYN>>>(
        bhi, blo, whi + WOFF_SIN, wlo + WOFF_SIN, s_b_in,
        nullptr, nullptr, nullptr, qkv, nullptr, nullptr, 384);
    // 5) spatial attention (HMMA) -> split
    spatial_attn_mma_kernel<<<dim3(Hdim, BTSEQ, 3), 256, SA_SMEM>>>(qkv, gbias, ahi, alo);
    // 6) spatial out-proj + res + LN -> x2 fp32 + split (reuse xhi/xlo)
    mm_kernel<128, 2, true><<<dim3(1, MTILES), 256, SMEM_DYN>>>(
        ahi, alo, whi + WOFF_SOUT, wlo + WOFF_SOUT, s_b_out,
        x1f, nsg, nsb, x2f, xhi, xlo, 128);
    // 7) FFN up + GELU -> split hbuf
    mm_kernel<128, 1, false><<<dim3(4, MTILES), 256, SMEM_DYN>>>(
        xhi, xlo, whi + WOFF_FF1, wlo + WOFF_FF1, ffb1,
        nullptr, nullptr, nullptr, nullptr, hhi, hlo, 512);
    // 8) FFN down + res + LN -> final output
    mm_kernel<512, 2, false><<<dim3(1, MTILES), 256, SMEM_DYN>>>(
        hhi, hlo, whi + WOFF_FF2, wlo + WOFF_FF2, ffb2,
        x2f, nfg, nfb, out, nullptr, nullptr, 128);
}

// round 13
// speedup vs baseline: 1.4060x; 1.0515x over previous
#include <cuda_runtime.h>
#include <cuda_bf16.h>
#include <math.h>
#include <stddef.h>
#include <stdint.h>

// ---------------- problem constants ----------------
#define Bdim 32
#define Tdim 12
#define Ndim 325
#define Ddim 128
#define Hdim 8
#define Fdim 512
#define BTN  124800          // B*T*N tokens
#define BNSEQ 10400          // B*N temporal sequences
#define BTSEQ 384            // B*T spatial sequences
#define MTILES 975           // BTN / 128

// ---------------- scratch (no-alloc rule: __device__ globals) ----------------
static __device__ float g_qkv[(size_t)BTN * 384];
static __device__ float g_x1f[(size_t)BTN * 128];
static __device__ float g_x2f[(size_t)BTN * 128];
static __device__ __nv_bfloat16 g_xhi[(size_t)BTN * 128];
static __device__ __nv_bfloat16 g_xlo[(size_t)BTN * 128];
static __device__ __nv_bfloat16 g_ahi[(size_t)BTN * 128];
static __device__ __nv_bfloat16 g_alo[(size_t)BTN * 128];
static __device__ __nv_bfloat16 g_bhi[(size_t)BTN * 128];
static __device__ __nv_bfloat16 g_blo[(size_t)BTN * 128];
static __device__ __nv_bfloat16 g_hhi[(size_t)BTN * 512];
static __device__ __nv_bfloat16 g_hlo[(size_t)BTN * 512];
static __device__ __nv_bfloat16 g_whi[262144];
static __device__ __nv_bfloat16 g_wlo[262144];
// weight offsets inside g_whi/g_wlo (elements)
#define WOFF_TIN  0
#define WOFF_SIN  49152
#define WOFF_TOUT 98304
#define WOFF_SOUT 114688
#define WOFF_FF1  131072
#define WOFF_FF2  196608

// ---------------- helpers ----------------
__device__ __forceinline__ uint32_t smem_u32(const void* p) {
    uint32_t a;
    asm("{ .reg .u64 t; cvta.to.shared.u64 t, %1; cvt.u32.u64 %0, t; }" : "=r"(a) : "l"(p));
    return a;
}
__device__ __forceinline__ void split1(float x, __nv_bfloat16& h, __nv_bfloat16& l) {
    h = __float2bfloat16(x);
    l = __float2bfloat16(x - __bfloat162float(h));
}
__device__ __forceinline__ float gelu_tanh(float v) {
    float c = 0.7978845608028654f * (v + 0.044715f * v * v * v);
    return 0.5f * v * (1.0f + tanhf(c));
}
__device__ __forceinline__ void ldm4(uint32_t* r, uint32_t addr) {
    asm volatile("ldmatrix.sync.aligned.m8n8.x4.shared.b16 {%0,%1,%2,%3}, [%4];"
                 : "=r"(r[0]), "=r"(r[1]), "=r"(r[2]), "=r"(r[3]) : "r"(addr));
}
__device__ __forceinline__ void mma_bf16(float* c, const uint32_t* a, const uint32_t* b) {
    asm volatile(
        "mma.sync.aligned.m16n8k16.row.col.f32.bf16.bf16.f32 "
        "{%0,%1,%2,%3}, {%4,%5,%6,%7}, {%8,%9}, {%0,%1,%2,%3};"
        : "+f"(c[0]), "+f"(c[1]), "+f"(c[2]), "+f"(c[3])
        : "r"(a[0]), "r"(a[1]), "r"(a[2]), "r"(a[3]), "r"(b[0]), "r"(b[1]));
}
__device__ __forceinline__ void cp16(uint32_t s, const void* g) {
    asm volatile("cp.async.cg.shared.global [%0], [%1], 16;" :: "r"(s), "l"(g));
}
__device__ __forceinline__ uint32_t pkbf(__nv_bfloat16 a, __nv_bfloat16 b) {
    return ((uint32_t)__bfloat16_as_ushort(b) << 16) | (uint32_t)__bfloat16_as_ushort(a);
}

// ---------------- split-bf16 HMMA GEMM (R11-validated core, now occ=2) ----------------
#define ROWB   80
#define TILEB  10240
#define BUFB   40960
#define SMEM_DYN 81920

template <int KD, int EPI, bool WSPLIT>
__global__ __launch_bounds__(256, 2) void mm_kernel(
    const __nv_bfloat16* __restrict__ Ahi, const __nv_bfloat16* __restrict__ Alo,
    const __nv_bfloat16* __restrict__ Whi, const __nv_bfloat16* __restrict__ Wlo,
    const float* __restrict__ bias,
    const float* __restrict__ res, const float* __restrict__ gam, const float* __restrict__ bet,
    float* __restrict__ outF, __nv_bfloat16* __restrict__ outHi, __nv_bfloat16* __restrict__ outLo,
    int Nc)
{
    extern __shared__ __align__(16) char smem[];
    const uint32_t sb = smem_u32(smem);

    const int tid  = threadIdx.x;
    const int mblk = blockIdx.y * 128;
    const int nblk = blockIdx.x * 128;
    const int w    = tid >> 5;
    const int l    = tid & 31;
    const int wm   = w & 3;
    const int wn   = w >> 2;
    const int g    = l >> 2;
    const int tig  = l & 3;

    const uint32_t laneA = (uint32_t)(((((l >> 3) & 1) * 8 + (l & 7)) * ROWB) + ((l >> 4) & 1) * 16);
    const uint32_t laneB = (uint32_t)(((((l >> 4) & 1) * 8 + (l & 7)) * ROWB) + ((l >> 3) & 1) * 16);

    float c[2][8][4];
#pragma unroll
    for (int m = 0; m < 2; m++)
#pragma unroll
        for (int n = 0; n < 8; n++)
#pragma unroll
            for (int k = 0; k < 4; k++) c[m][n][k] = 0.0f;

    const __nv_bfloat16* gbase[4];
    gbase[0] = Ahi + (size_t)mblk * KD;
    gbase[1] = Alo + (size_t)mblk * KD;
    gbase[2] = Whi + (size_t)nblk * KD;
    gbase[3] = Wlo + (size_t)nblk * KD;

    int cpTile[8], cpRow[8], cpCh[8];
#pragma unroll
    for (int i = 0; i < 8; i++) {
        int idx  = tid + i * 256;
        cpTile[i] = idx >> 9;
        cpRow[i]  = (idx >> 2) & 127;
        cpCh[i]   = idx & 3;
    }

    const int nc = KD / 32;

#pragma unroll
    for (int i = 0; i < 8; i++)
        cp16(sb + cpTile[i] * TILEB + cpRow[i] * ROWB + cpCh[i] * 16,
             gbase[cpTile[i]] + (size_t)cpRow[i] * KD + cpCh[i] * 8);
    asm volatile("cp.async.commit_group;" ::: "memory");

    for (int cc = 0; cc < nc; cc++) {
        if (cc + 1 < nc) {
            const int k0 = (cc + 1) * 32;
            const uint32_t bb = sb + ((cc + 1) & 1) * BUFB;
#pragma unroll
            for (int i = 0; i < 8; i++)
                cp16(bb + cpTile[i] * TILEB + cpRow[i] * ROWB + cpCh[i] * 16,
                     gbase[cpTile[i]] + (size_t)cpRow[i] * KD + k0 + cpCh[i] * 8);
            asm volatile("cp.async.commit_group;" ::: "memory");
            asm volatile("cp.async.wait_group 1;" ::: "memory");
        } else {
            asm volatile("cp.async.wait_group 0;" ::: "memory");
        }
        __syncthreads();

        const uint32_t bb  = sb + (cc & 1) * BUFB;
        const uint32_t aHi = bb + (uint32_t)(wm * 32) * ROWB + laneA;
        const uint32_t aLo = aHi + TILEB;
        const uint32_t wHi = bb + 2 * TILEB + (uint32_t)(wn * 64) * ROWB + laneB;
        const uint32_t wLo = wHi + TILEB;

#pragma unroll
        for (int ks = 0; ks < 2; ks++) {
            const uint32_t kb = ks * 32;
            uint32_t ah[2][4], al[2][4], bh[4][4], bl[4][4];
            ldm4(ah[0], aHi + kb);
            ldm4(ah[1], aHi + 16 * ROWB + kb);
            ldm4(al[0], aLo + kb);
            ldm4(al[1], aLo + 16 * ROWB + kb);
#pragma unroll
            for (int i = 0; i < 4; i++) {
                ldm4(bh[i], wHi + (uint32_t)(i * 16) * ROWB + kb);
                ldm4(bl[i], wLo + (uint32_t)(i * 16) * ROWB + kb);
            }
#pragma unroll
            for (int m = 0; m < 2; m++)
#pragma unroll
                for (int i = 0; i < 4; i++) {
                    mma_bf16(c[m][2 * i],     ah[m], &bh[i][0]);
                    mma_bf16(c[m][2 * i],     ah[m], &bl[i][0]);
                    mma_bf16(c[m][2 * i],     al[m], &bh[i][0]);
                    mma_bf16(c[m][2 * i + 1], ah[m], &bh[i][2]);
                    mma_bf16(c[m][2 * i + 1], ah[m], &bl[i][2]);
                    mma_bf16(c[m][2 * i + 1], al[m], &bh[i][2]);
                }
        }
        __syncthreads();
    }

    float* Cs   = (float*)smem;
    float* redS = Cs + 128 * 132;
    float* redQ = redS + 256;
#pragma unroll
    for (int m = 0; m < 2; m++)
#pragma unroll
        for (int nb = 0; nb < 8; nb++) {
            const int row0 = wm * 32 + m * 16 + g;
            const int col0 = wn * 64 + nb * 8 + 2 * tig;
            *(float2*)&Cs[row0 * 132 + col0]       = make_float2(c[m][nb][0], c[m][nb][1]);
            *(float2*)&Cs[(row0 + 8) * 132 + col0] = make_float2(c[m][nb][2], c[m][nb][3]);
        }
    __syncthreads();

    const int r    = tid >> 1;
    const int half = tid & 1;
    const int grow = mblk + r;
    const int n0   = nblk + half * 64;
    const float* crow = Cs + r * 132 + half * 64;

    if (EPI == 0) {
#pragma unroll
        for (int cidx = 0; cidx < 64; cidx += 4) {
            float4 v  = *(const float4*)(crow + cidx);
            float4 b4 = *(const float4*)(bias + n0 + cidx);
            float4 o;
            o.x = v.x + b4.x; o.y = v.y + b4.y; o.z = v.z + b4.z; o.w = v.w + b4.w;
            *(float4*)(outF + (size_t)grow * Nc + n0 + cidx) = o;
        }
    } else if (EPI == 1) {
#pragma unroll
        for (int c8 = 0; c8 < 64; c8 += 8) {
            __nv_bfloat16 hv[8], lv[8];
#pragma unroll
            for (int j = 0; j < 8; j++) {
                float v = gelu_tanh(crow[c8 + j] + bias[n0 + c8 + j]);
                split1(v, hv[j], lv[j]);
            }
            *(uint4*)(outHi + (size_t)grow * Nc + n0 + c8) = *(uint4*)hv;
            *(uint4*)(outLo + (size_t)grow * Nc + n0 + c8) = *(uint4*)lv;
        }
    } else {
        float vv[64];
        float s = 0.0f, q = 0.0f;
#pragma unroll
        for (int cidx = 0; cidx < 64; cidx += 4) {
            float4 v  = *(const float4*)(crow + cidx);
            float4 b4 = *(const float4*)(bias + n0 + cidx);
            float4 r4 = *(const float4*)(res + (size_t)grow * 128 + n0 + cidx);
            vv[cidx + 0] = v.x + b4.x + r4.x;
            vv[cidx + 1] = v.y + b4.y + r4.y;
            vv[cidx + 2] = v.z + b4.z + r4.z;
            vv[cidx + 3] = v.w + b4.w + r4.w;
#pragma unroll
            for (int j = 0; j < 4; j++) {
                s += vv[cidx + j];
                q = fmaf(vv[cidx + j], vv[cidx + j], q);
            }
        }
        redS[half * 128 + r] = s;
        redQ[half * 128 + r] = q;
        __syncthreads();
        const float ts = redS[r] + redS[128 + r];
        const float tq = redQ[r] + redQ[128 + r];
        const float mean = ts * (1.0f / 128.0f);
        const float var  = tq * (1.0f / 128.0f) - mean * mean;
        const float rstd = rsqrtf(var + 1e-5f);
#pragma unroll
        for (int c8 = 0; c8 < 64; c8 += 8) {
            float ov[8];
#pragma unroll
            for (int j = 0; j < 8; j++) {
                const int cidx = c8 + j;
                ov[j] = (vv[cidx] - mean) * rstd * gam[n0 + cidx] + bet[n0 + cidx];
            }
            *(float4*)(outF + (size_t)grow * 128 + n0 + c8)     = *(float4*)&ov[0];
            *(float4*)(outF + (size_t)grow * 128 + n0 + c8 + 4) = *(float4*)&ov[4];
            if (WSPLIT) {
                __nv_bfloat16 hv[8], lv[8];
#pragma unroll
                for (int j = 0; j < 8; j++) split1(ov[j], hv[j], lv[j]);
                *(uint4*)(outHi + (size_t)grow * 128 + n0 + c8) = *(uint4*)hv;
                *(uint4*)(outLo + (size_t)grow * 128 + n0 + c8) = *(uint4*)lv;
            }
        }
    }
}

// ---------------- convert fp32 -> bf16 hi/lo ----------------
__global__ __launch_bounds__(256) void convert_split_kernel(
    const float* __restrict__ in, __nv_bfloat16* __restrict__ hi,
    __nv_bfloat16* __restrict__ lo, int n4)
{
    int i = blockIdx.x * 256 + threadIdx.x;
    if (i < n4) {
        float4 v = ((const float4*)in)[i];
        __nv_bfloat16 h[4], l[4];
        split1(v.x, h[0], l[0]); split1(v.y, h[1], l[1]);
        split1(v.z, h[2], l[2]); split1(v.w, h[3], l[3]);
        ((uint2*)hi)[i] = *(uint2*)h;
        ((uint2*)lo)[i] = *(uint2*)l;
    }
}

// ---------------- temporal attention (scalar, split output) ----------------
__global__ __launch_bounds__(128) void temporal_attn_kernel(
    const float* __restrict__ qkv, __nv_bfloat16* __restrict__ ohi,
    __nv_bfloat16* __restrict__ olo)
{
    __shared__ __align__(16) float sq[Tdim][388];
    const int bn  = blockIdx.x;
    const int b   = bn / Ndim;
    const int n   = bn % Ndim;
    const int tid = threadIdx.x;

    for (int idx = tid; idx < Tdim * 96; idx += 128) {
        int t = idx / 96;
        int c = (idx % 96) * 4;
        size_t rr = ((size_t)(b * Tdim + t) * Ndim + n) * 384;
        *(float4*)&sq[t][c] = *(const float4*)(qkv + rr + c);
    }
    __syncthreads();

    if (tid < Hdim * Tdim) {
        const int h   = tid / Tdim;
        const int q   = tid % Tdim;
        const int off = h * 16;
        float qd[16];
#pragma unroll
        for (int d = 0; d < 16; d++) qd[d] = sq[q][off + d];
        float e[Tdim], Z = 0.0f;
#pragma unroll
        for (int s = 0; s < Tdim; s++) {
            float sc = 0.0f;
#pragma unroll
            for (int d = 0; d < 16; d++) sc = fmaf(qd[d], sq[s][128 + off + d], sc);
            e[s] = __expf(sc * 0.25f);
            Z += e[s];
        }
        float inv = 1.0f / Z;
        __nv_bfloat16 hv[16], lv[16];
#pragma unroll
        for (int d = 0; d < 16; d++) {
            float a = 0.0f;
#pragma unroll
            for (int s = 0; s < Tdim; s++) a = fmaf(e[s], sq[s][256 + off + d], a);
            split1(a * inv, hv[d], lv[d]);
        }
        size_t ro = ((size_t)(b * Tdim + q) * Ndim + n) * 128 + off;
        *(uint4*)(ohi + ro)     = *(uint4*)&hv[0];
        *(uint4*)(ohi + ro + 8) = *(uint4*)&hv[8];
        *(uint4*)(olo + ro)     = *(uint4*)&lv[0];
        *(uint4*)(olo + ro + 8) = *(uint4*)&lv[8];
    }
}

// ---------------- spatial attention: HMMA flash-style (no-max softmax), occ=2 ----------------
#define SA_SMEM 108032

__global__ __launch_bounds__(256, 2) void spatial_attn_mma_kernel(
    const float* __restrict__ qkv, const float* __restrict__ gbias,
    __nv_bfloat16* __restrict__ ohi, __nv_bfloat16* __restrict__ olo)
{
    extern __shared__ __align__(16) char smem[];
    __nv_bfloat16* sp = (__nv_bfloat16*)smem;
    float* bs = (float*)(smem + 74240);
    const uint32_t sb = smem_u32(smem);

    const int h   = blockIdx.x;
    const int bt  = blockIdx.y;
    const int q0  = blockIdx.z * 128;
    const int tid = threadIdx.x;
    const int w   = tid >> 5, l = tid & 31;
    const int g   = l >> 2, tig = l & 3;
    const size_t base = (size_t)bt * Ndim * 384;

    for (int e = tid; e < 2048; e += 256) {
        int row = e >> 4, d = e & 15;
        float v = (q0 + row < Ndim) ? qkv[base + (size_t)(q0 + row) * 384 + h * 16 + d] : 0.f;
        __nv_bfloat16 hb, lb; split1(v, hb, lb);
        sp[row * 24 + d] = hb; sp[3072 + row * 24 + d] = lb;
    }
    for (int e = tid; e < 6144; e += 256) {
        int row = e >> 4, d = e & 15;
        float kv = (row < Ndim) ? qkv[base + (size_t)row * 384 + 128 + h * 16 + d] : 0.f;
        __nv_bfloat16 hb, lb; split1(kv, hb, lb);
        sp[6144 + row * 24 + d] = hb; sp[15360 + row * 24 + d] = lb;
        float vv = (row < Ndim) ? qkv[base + (size_t)row * 384 + 256 + h * 16 + d] : 0.f;
        split1(vv, hb, lb);
        sp[24576 + d * 392 + row] = hb; sp[30848 + d * 392 + row] = lb;
    }
    __syncthreads();

    const uint32_t laneA = (uint32_t)((((l >> 3) & 1) * 8 + (l & 7)) * 48 + ((l >> 4) & 1) * 16);
    const uint32_t laneB = (uint32_t)((((l >> 4) & 1) * 8 + (l & 7)) * 48 + ((l >> 3) & 1) * 16);
    const uint32_t laneV = (uint32_t)((((l >> 4) & 1) * 8 + (l & 7)) * 784 + ((l >> 3) & 1) * 16);

    uint32_t qh4[4], ql4[4];
    ldm4(qh4, sb + 0    + (uint32_t)(w * 16) * 48 + laneA);
    ldm4(ql4, sb + 6144 + (uint32_t)(w * 16) * 48 + laneA);

    float o0[4] = {0.f, 0.f, 0.f, 0.f}, o1[4] = {0.f, 0.f, 0.f, 0.f};
    float zg = 0.f, zh = 0.f;
    const int r0 = w * 16 + g, r1 = r0 + 8;

    for (int ch = 0; ch < 6; ch++) {
        __syncthreads();
        for (int e = tid; e < 8192; e += 256) {
            int row = e >> 6, col = e & 63;
            int qq = q0 + row, jj = ch * 64 + col;
            bs[row * 66 + col] = (qq < Ndim && jj < Ndim) ? gbias[qq * Ndim + jj] : 0.f;
        }
        __syncthreads();

        float s[8][4];
#pragma unroll
        for (int t = 0; t < 8; t++)
#pragma unroll
            for (int k = 0; k < 4; k++) s[t][k] = 0.f;
#pragma unroll
        for (int i = 0; i < 4; i++) {
            uint32_t kh[4], kl[4];
            ldm4(kh, sb + 12288 + (uint32_t)(ch * 64 + i * 16) * 48 + laneB);
            ldm4(kl, sb + 30720 + (uint32_t)(ch * 64 + i * 16) * 48 + laneB);
            mma_bf16(s[2 * i],     qh4, &kh[0]);
            mma_bf16(s[2 * i],     qh4, &kl[0]);
            mma_bf16(s[2 * i],     ql4, &kh[0]);
            mma_bf16(s[2 * i + 1], qh4, &kh[2]);
            mma_bf16(s[2 * i + 1], qh4, &kl[2]);
            mma_bf16(s[2 * i + 1], ql4, &kh[2]);
        }

        uint32_t pah[4][4], pal[4][4];
#pragma unroll
        for (int t = 0; t < 8; t++) {
            const int f = t >> 1, hf = t & 1;
            const int jl = f * 16 + hf * 8 + 2 * tig;
            const int jglob = ch * 64 + jl;
            float p0 = (jglob     < Ndim) ? __expf(fmaf(s[t][0], 0.25f, bs[r0 * 66 + jl]))     : 0.f;
            float p1 = (jglob + 1 < Ndim) ? __expf(fmaf(s[t][1], 0.25f, bs[r0 * 66 + jl + 1])) : 0.f;
            float p2 = (jglob     < Ndim) ? __expf(fmaf(s[t][2], 0.25f, bs[r1 * 66 + jl]))     : 0.f;
            float p3 = (jglob + 1 < Ndim) ? __expf(fmaf(s[t][3], 0.25f, bs[r1 * 66 + jl + 1])) : 0.f;
            zg += p0 + p1; zh += p2 + p3;
            __nv_bfloat16 h0, l0, h1, l1, h2, l2, h3, l3;
            split1(p0, h0, l0); split1(p1, h1, l1);
            split1(p2, h2, l2); split1(p3, h3, l3);
            pah[f][hf * 2 + 0] = pkbf(h0, h1);
            pah[f][hf * 2 + 1] = pkbf(h2, h3);
            pal[f][hf * 2 + 0] = pkbf(l0, l1);
            pal[f][hf * 2 + 1] = pkbf(l2, l3);
        }

#pragma unroll
        for (int kf = 0; kf < 4; kf++) {
            uint32_t vh[4], vl[4];
            ldm4(vh, sb + 49152 + laneV + (uint32_t)(ch * 64 + kf * 16) * 2);
            ldm4(vl, sb + 61696 + laneV + (uint32_t)(ch * 64 + kf * 16) * 2);
            mma_bf16(o0, pah[kf], &vh[0]);
            mma_bf16(o0, pah[kf], &vl[0]);
            mma_bf16(o0, pal[kf], &vh[0]);
            mma_bf16(o1, pah[kf], &vh[2]);
            mma_bf16(o1, pah[kf], &vl[2]);
            mma_bf16(o1, pal[kf], &vh[2]);
        }
    }

    zg += __shfl_xor_sync(0xffffffffu, zg, 1);
    zg += __shfl_xor_sync(0xffffffffu, zg, 2);
    zh += __shfl_xor_sync(0xffffffffu, zh, 1);
    zh += __shfl_xor_sync(0xffffffffu, zh, 2);
    const float ig = 1.f / zg, ih = 1.f / zh;

    const int qg = q0 + r0;
    if (qg < Ndim) {
        size_t rb = ((size_t)bt * Ndim + qg) * 128 + h * 16;
        __nv_bfloat16 ha, la, hb2, lb2;
        split1(o0[0] * ig, ha, la); split1(o0[1] * ig, hb2, lb2);
        *(uint32_t*)(ohi + rb + 2 * tig) = pkbf(ha, hb2);
        *(uint32_t*)(olo + rb + 2 * tig) = pkbf(la, lb2);
        split1(o1[0] * ig, ha, la); split1(o1[1] * ig, hb2, lb2);
        *(uint32_t*)(ohi + rb + 8 + 2 * tig) = pkbf(ha, hb2);
        *(uint32_t*)(olo + rb + 8 + 2 * tig) = pkbf(la, lb2);
    }
    const int qh8 = q0 + r1;
    if (qh8 < Ndim) {
        size_t rb = ((size_t)bt * Ndim + qh8) * 128 + h * 16;
        __nv_bfloat16 ha, la, hb2, lb2;
        split1(o0[2] * ih, ha, la); split1(o0[3] * ih, hb2, lb2);
        *(uint32_t*)(ohi + rb + 2 * tig) = pkbf(ha, hb2);
        *(uint32_t*)(olo + rb + 2 * tig) = pkbf(la, lb2);
        split1(o1[2] * ih, ha, la); split1(o1[3] * ih, hb2, lb2);
        *(uint32_t*)(ohi + rb + 8 + 2 * tig) = pkbf(ha, hb2);
        *(uint32_t*)(olo + rb + 8 + 2 * tig) = pkbf(la, lb2);
    }
}

// ---------------- launch ----------------
extern "C" void kernel_launch(void* const* d_in, const int* in_sizes, int n_in,
                              void* d_out, int out_size)
{
    const float* x       = (const float*)d_in[0];
    const float* t_w_in  = (const float*)d_in[1];
    const float* t_b_in  = (const float*)d_in[2];
    const float* t_w_out = (const float*)d_in[3];
    const float* t_b_out = (const float*)d_in[4];
    const float* s_w_in  = (const float*)d_in[5];
    const float* s_b_in  = (const float*)d_in[6];
    const float* s_w_out = (const float*)d_in[7];
    const float* s_b_out = (const float*)d_in[8];
    const float* gbias   = (const float*)d_in[9];
    const float* ntg     = (const float*)d_in[10];
    const float* ntb     = (const float*)d_in[11];
    const float* nsg     = (const float*)d_in[12];
    const float* nsb     = (const float*)d_in[13];
    const float* ffw1    = (const float*)d_in[14];
    const float* ffb1    = (const float*)d_in[15];
    const float* ffw2    = (const float*)d_in[16];
    const float* ffb2    = (const float*)d_in[17];
    const float* nfg     = (const float*)d_in[18];
    const float* nfb     = (const float*)d_in[19];
    float* out = (float*)d_out;

    float *qkv, *x1f, *x2f;
    __nv_bfloat16 *xhi, *xlo, *ahi, *alo, *bhi, *blo, *hhi, *hlo, *whi, *wlo;
    cudaGetSymbolAddress((void**)&qkv, g_qkv);
    cudaGetSymbolAddress((void**)&x1f, g_x1f);
    cudaGetSymbolAddress((void**)&x2f, g_x2f);
    cudaGetSymbolAddress((void**)&xhi, g_xhi);
    cudaGetSymbolAddress((void**)&xlo, g_xlo);
    cudaGetSymbolAddress((void**)&ahi, g_ahi);
    cudaGetSymbolAddress((void**)&alo, g_alo);
    cudaGetSymbolAddress((void**)&bhi, g_bhi);
    cudaGetSymbolAddress((void**)&blo, g_blo);
    cudaGetSymbolAddress((void**)&hhi, g_hhi);
    cudaGetSymbolAddress((void**)&hlo, g_hlo);
    cudaGetSymbolAddress((void**)&whi, g_whi);
    cudaGetSymbolAddress((void**)&wlo, g_wlo);

    cudaFuncSetAttribute(mm_kernel<128, 0, false>, cudaFuncAttributeMaxDynamicSharedMemorySize, SMEM_DYN);
    cudaFuncSetAttribute(mm_kernel<128, 1, false>, cudaFuncAttributeMaxDynamicSharedMemorySize, SMEM_DYN);
    cudaFuncSetAttribute(mm_kernel<128, 2, true >, cudaFuncAttributeMaxDynamicSharedMemorySize, SMEM_DYN);
    cudaFuncSetAttribute(mm_kernel<512, 2, false>, cudaFuncAttributeMaxDynamicSharedMemorySize, SMEM_DYN);
    cudaFuncSetAttribute(spatial_attn_mma_kernel, cudaFuncAttributeMaxDynamicSharedMemorySize, SA_SMEM);

    // converts needed for phase 1-6 (ordered so launch index 5 = QKV mm_kernel for ncu -s 5 -c 1)
    convert_split_kernel<<<(BTN * 128 / 4 + 255) / 256, 256>>>(x, xhi, xlo, BTN * 128 / 4);  // 0
    convert_split_kernel<<<48, 256>>>(t_w_in,  whi + WOFF_TIN,  wlo + WOFF_TIN,  49152 / 4); // 1
    convert_split_kernel<<<16, 256>>>(t_w_out, whi + WOFF_TOUT, wlo + WOFF_TOUT, 16384 / 4); // 2
    convert_split_kernel<<<48, 256>>>(s_w_in,  whi + WOFF_SIN,  wlo + WOFF_SIN,  49152 / 4); // 3
    convert_split_kernel<<<16, 256>>>(s_w_out, whi + WOFF_SOUT, wlo + WOFF_SOUT, 16384 / 4); // 4

    // 1) temporal QKV   (launch index 5 -> profiled)
    mm_kernel<128, 0, false><<<dim3(3, MTILES), 256, SMEM_DYN>>>(
        xhi, xlo, whi + WOFF_TIN, wlo + WOFF_TIN, t_b_in,
        nullptr, nullptr, nullptr, qkv, nullptr, nullptr, 384);
    // 2) temporal attention -> split
    temporal_attn_kernel<<<BNSEQ, 128>>>(qkv, ahi, alo);
    // 3) temporal out-proj + res + LN -> x1 fp32 + split (bhi/blo)
    mm_kernel<128, 2, true><<<dim3(1, MTILES), 256, SMEM_DYN>>>(
        ahi, alo, whi + WOFF_TOUT, wlo + WOFF_TOUT, t_b_out,
        x, ntg, ntb, x1f, bhi, blo, 128);
    // 4) spatial QKV
    mm_kernel<128, 0, false><<<dim3(3, MTILES), 256, SMEM_DYN>>>(
        bhi, blo, whi + WOFF_SIN, wlo + WOFF_SIN, s_b_in,
        nullptr, nullptr, nullptr, qkv, nullptr, nullptr, 384);
    // 5) spatial attention (HMMA) -> split
    spatial_attn_mma_kernel<<<dim3(Hdim, BTSEQ, 3), 256, SA_SMEM>>>(qkv, gbias, ahi, alo);
    // 6) spatial out-proj + res + LN -> x2 fp32 + split (reuse xhi/xlo)
    mm_kernel<128, 2, true><<<dim3(1, MTILES), 256, SMEM_DYN>>>(
        ahi, alo, whi + WOFF_SOUT, wlo + WOFF_SOUT, s_b_out,
        x1f, nsg, nsb, x2f, xhi, xlo, 128);
    // converts for FFN weights
    convert_split_kernel<<<64, 256>>>(ffw1, whi + WOFF_FF1, wlo + WOFF_FF1, 65536 / 4);
    convert_split_kernel<<<64, 256>>>(ffw2, whi + WOFF_FF2, wlo + WOFF_FF2, 65536 / 4);
    // 7) FFN up + GELU -> split hbuf
    mm_kernel<128, 1, false><<<dim3(4, MTILES), 256, SMEM_DYN>>>(
        xhi, xlo, whi + WOFF_FF1, wlo + WOFF_FF1, ffb1,
        nullptr, nullptr, nullptr, nullptr, hhi, hlo, 512);
    // 8) FFN down + res + LN -> final output
    mm_kernel<512, 2, false><<<dim3(1, MTILES), 256, SMEM_DYN>>>(
        hhi, hlo, whi + WOFF_FF2, wlo + WOFF_FF2, ffb2,
        x2f, nfg, nfb, out, nullptr, nullptr, 128);
}

// round 14
// speedup vs baseline: 1.7594x; 1.2513x over previous
#include <cuda_runtime.h>
#include <cuda_fp16.h>
#include <math.h>
#include <stddef.h>
#include <stdint.h>

// ---------------- problem constants ----------------
#define Bdim 32
#define Tdim 12
#define Ndim 325
#define Ddim 128
#define Hdim 8
#define Fdim 512
#define BTN  124800          // B*T*N tokens
#define BNSEQ 10400
#define BTSEQ 384
#define MTILES 975           // BTN / 128

// ---------------- scratch (no-alloc rule: __device__ globals) ----------------
static __device__ float g_qkv[(size_t)BTN * 384];
static __device__ float g_x1f[(size_t)BTN * 128];
static __device__ float g_x2f[(size_t)BTN * 128];
static __device__ __half g_xh[(size_t)BTN * 128];
static __device__ __half g_ah[(size_t)BTN * 128];
static __device__ __half g_bh[(size_t)BTN * 128];
static __device__ __half g_hh[(size_t)BTN * 512];
static __device__ __half g_wh[262144];
// weight offsets inside g_wh (elements)
#define WOFF_TIN  0
#define WOFF_SIN  49152
#define WOFF_TOUT 98304
#define WOFF_SOUT 114688
#define WOFF_FF1  131072
#define WOFF_FF2  196608

// ---------------- helpers ----------------
__device__ __forceinline__ uint32_t smem_u32(const void* p) {
    uint32_t a;
    asm("{ .reg .u64 t; cvta.to.shared.u64 t, %1; cvt.u32.u64 %0, t; }" : "=r"(a) : "l"(p));
    return a;
}
__device__ __forceinline__ float gelu_tanh(float v) {
    float c = 0.7978845608028654f * (v + 0.044715f * v * v * v);
    return 0.5f * v * (1.0f + tanhf(c));
}
__device__ __forceinline__ void ldm4(uint32_t* r, uint32_t addr) {
    asm volatile("ldmatrix.sync.aligned.m8n8.x4.shared.b16 {%0,%1,%2,%3}, [%4];"
                 : "=r"(r[0]), "=r"(r[1]), "=r"(r[2]), "=r"(r[3]) : "r"(addr));
}
__device__ __forceinline__ void mma_f16(float* c, const uint32_t* a, const uint32_t* b) {
    asm volatile(
        "mma.sync.aligned.m16n8k16.row.col.f32.f16.f16.f32 "
        "{%0,%1,%2,%3}, {%4,%5,%6,%7}, {%8,%9}, {%0,%1,%2,%3};"
        : "+f"(c[0]), "+f"(c[1]), "+f"(c[2]), "+f"(c[3])
        : "r"(a[0]), "r"(a[1]), "r"(a[2]), "r"(a[3]), "r"(b[0]), "r"(b[1]));
}
__device__ __forceinline__ void cp16(uint32_t s, const void* g) {
    asm volatile("cp.async.cg.shared.global [%0], [%1], 16;" :: "r"(s), "l"(g));
}
__device__ __forceinline__ uint32_t pkh(__half a, __half b) {
    return ((uint32_t)__half_as_ushort(b) << 16) | (uint32_t)__half_as_ushort(a);
}

// ---------------- single-fp16 HMMA GEMM ----------------
// C[M,Nc] = A[M,KD] @ W[Nc,KD]^T  (fp16 operands, fp32 accum)
// EPI 0: out = D + bias (fp32)
// EPI 1: out = gelu(D + bias) -> fp16
// EPI 2: out = LN(D + bias + res) -> fp32 (+ fp16 if WH); Nc==128, nblk==0
#define ROWB   80                  // 32 fp16 = 64B data + 16B pad
#define TILEB  10240               // 128 rows x 80B
#define BUFB   20480               // 2 tiles (A, W)
#define SMEM_DYN 69632             // epilogue: 128x132 f32 + 2x256 f32

template <int KD, int EPI, bool WH>
__global__ __launch_bounds__(256, 2) void mm_kernel(
    const __half* __restrict__ A, const __half* __restrict__ W,
    const float* __restrict__ bias,
    const float* __restrict__ res, const float* __restrict__ gam, const float* __restrict__ bet,
    float* __restrict__ outF, __half* __restrict__ outH, int Nc)
{
    extern __shared__ __align__(16) char smem[];
    const uint32_t sb = smem_u32(smem);

    const int tid  = threadIdx.x;
    const int mblk = blockIdx.y * 128;
    const int nblk = blockIdx.x * 128;
    const int w    = tid >> 5;
    const int l    = tid & 31;
    const int wm   = w & 3;
    const int wn   = w >> 2;
    const int g    = l >> 2;
    const int tig  = l & 3;

    const uint32_t laneA = (uint32_t)(((((l >> 3) & 1) * 8 + (l & 7)) * ROWB) + ((l >> 4) & 1) * 16);
    const uint32_t laneB = (uint32_t)(((((l >> 4) & 1) * 8 + (l & 7)) * ROWB) + ((l >> 3) & 1) * 16);

    float c[2][8][4];
#pragma unroll
    for (int m = 0; m < 2; m++)
#pragma unroll
        for (int n = 0; n < 8; n++)
#pragma unroll
            for (int k = 0; k < 4; k++) c[m][n][k] = 0.0f;

    const __half* gbase[2];
    gbase[0] = A + (size_t)mblk * KD;
    gbase[1] = W + (size_t)nblk * KD;

    // 1024 16B-chunks = [tile(2)][row(128)][ch(4)]; 4 per thread
    int cpTile[4], cpRow[4], cpCh[4];
#pragma unroll
    for (int i = 0; i < 4; i++) {
        int idx  = tid + i * 256;
        cpTile[i] = idx >> 9;
        cpRow[i]  = (idx >> 2) & 127;
        cpCh[i]   = idx & 3;
    }

    const int nc = KD / 32;

#pragma unroll
    for (int i = 0; i < 4; i++)
        cp16(sb + cpTile[i] * TILEB + cpRow[i] * ROWB + cpCh[i] * 16,
             gbase[cpTile[i]] + (size_t)cpRow[i] * KD + cpCh[i] * 8);
    asm volatile("cp.async.commit_group;" ::: "memory");

    for (int cc = 0; cc < nc; cc++) {
        if (cc + 1 < nc) {
            const int k0 = (cc + 1) * 32;
            const uint32_t bb = sb + ((cc + 1) & 1) * BUFB;
#pragma unroll
            for (int i = 0; i < 4; i++)
                cp16(bb + cpTile[i] * TILEB + cpRow[i] * ROWB + cpCh[i] * 16,
                     gbase[cpTile[i]] + (size_t)cpRow[i] * KD + k0 + cpCh[i] * 8);
            asm volatile("cp.async.commit_group;" ::: "memory");
            asm volatile("cp.async.wait_group 1;" ::: "memory");
        } else {
            asm volatile("cp.async.wait_group 0;" ::: "memory");
        }
        __syncthreads();

        const uint32_t bb = sb + (cc & 1) * BUFB;
        const uint32_t aP = bb + (uint32_t)(wm * 32) * ROWB + laneA;
        const uint32_t wP = bb + TILEB + (uint32_t)(wn * 64) * ROWB + laneB;

#pragma unroll
        for (int ks = 0; ks < 2; ks++) {
            const uint32_t kb = ks * 32;
            uint32_t a4[2][4], b4[4][4];
            ldm4(a4[0], aP + kb);
            ldm4(a4[1], aP + 16 * ROWB + kb);
#pragma unroll
            for (int i = 0; i < 4; i++)
                ldm4(b4[i], wP + (uint32_t)(i * 16) * ROWB + kb);
#pragma unroll
            for (int m = 0; m < 2; m++)
#pragma unroll
                for (int i = 0; i < 4; i++) {
                    mma_f16(c[m][2 * i],     a4[m], &b4[i][0]);
                    mma_f16(c[m][2 * i + 1], a4[m], &b4[i][2]);
                }
        }
        __syncthreads();
    }

    // ---- stage C through smem ----
    float* Cs   = (float*)smem;                 // [128][132]
    float* redS = Cs + 128 * 132;
    float* redQ = redS + 256;
#pragma unroll
    for (int m = 0; m < 2; m++)
#pragma unroll
        for (int nb = 0; nb < 8; nb++) {
            const int row0 = wm * 32 + m * 16 + g;
            const int col0 = wn * 64 + nb * 8 + 2 * tig;
            *(float2*)&Cs[row0 * 132 + col0]       = make_float2(c[m][nb][0], c[m][nb][1]);
            *(float2*)&Cs[(row0 + 8) * 132 + col0] = make_float2(c[m][nb][2], c[m][nb][3]);
        }
    __syncthreads();

    const int r    = tid >> 1;
    const int half = tid & 1;
    const int grow = mblk + r;
    const int n0   = nblk + half * 64;
    const float* crow = Cs + r * 132 + half * 64;

    if (EPI == 0) {
#pragma unroll
        for (int cidx = 0; cidx < 64; cidx += 4) {
            float4 v  = *(const float4*)(crow + cidx);
            float4 b4 = *(const float4*)(bias + n0 + cidx);
            float4 o;
            o.x = v.x + b4.x; o.y = v.y + b4.y; o.z = v.z + b4.z; o.w = v.w + b4.w;
            *(float4*)(outF + (size_t)grow * Nc + n0 + cidx) = o;
        }
    } else if (EPI == 1) {
#pragma unroll
        for (int c8 = 0; c8 < 64; c8 += 8) {
            __half hv[8];
#pragma unroll
            for (int j = 0; j < 8; j++)
                hv[j] = __float2half(gelu_tanh(crow[c8 + j] + bias[n0 + c8 + j]));
            *(uint4*)(outH + (size_t)grow * Nc + n0 + c8) = *(uint4*)hv;
        }
    } else {
        float vv[64];
        float s = 0.0f, q = 0.0f;
#pragma unroll
        for (int cidx = 0; cidx < 64; cidx += 4) {
            float4 v  = *(const float4*)(crow + cidx);
            float4 b4 = *(const float4*)(bias + n0 + cidx);
            float4 r4 = *(const float4*)(res + (size_t)grow * 128 + n0 + cidx);
            vv[cidx + 0] = v.x + b4.x + r4.x;
            vv[cidx + 1] = v.y + b4.y + r4.y;
            vv[cidx + 2] = v.z + b4.z + r4.z;
            vv[cidx + 3] = v.w + b4.w + r4.w;
#pragma unroll
            for (int j = 0; j < 4; j++) {
                s += vv[cidx + j];
                q = fmaf(vv[cidx + j], vv[cidx + j], q);
            }
        }
        redS[half * 128 + r] = s;
        redQ[half * 128 + r] = q;
        __syncthreads();
        const float ts = redS[r] + redS[128 + r];
        const float tq = redQ[r] + redQ[128 + r];
        const float mean = ts * (1.0f / 128.0f);
        const float var  = tq * (1.0f / 128.0f) - mean * mean;
        const float rstd = rsqrtf(var + 1e-5f);
#pragma unroll
        for (int c8 = 0; c8 < 64; c8 += 8) {
            float ov[8];
#pragma unroll
            for (int j = 0; j < 8; j++) {
                const int cidx = c8 + j;
                ov[j] = (vv[cidx] - mean) * rstd * gam[n0 + cidx] + bet[n0 + cidx];
            }
            *(float4*)(outF + (size_t)grow * 128 + n0 + c8)     = *(float4*)&ov[0];
            *(float4*)(outF + (size_t)grow * 128 + n0 + c8 + 4) = *(float4*)&ov[4];
            if (WH) {
                __half hv[8];
#pragma unroll
                for (int j = 0; j < 8; j++) hv[j] = __float2half(ov[j]);
                *(uint4*)(outH + (size_t)grow * 128 + n0 + c8) = *(uint4*)hv;
            }
        }
    }
}

// ---------------- convert fp32 -> fp16 ----------------
__global__ __launch_bounds__(256) void convert_h_kernel(
    const float* __restrict__ in, __half* __restrict__ out, int n4)
{
    int i = blockIdx.x * 256 + threadIdx.x;
    if (i < n4) {
        float4 v = ((const float4*)in)[i];
        __half h[4];
        h[0] = __float2half(v.x); h[1] = __float2half(v.y);
        h[2] = __float2half(v.z); h[3] = __float2half(v.w);
        ((uint2*)out)[i] = *(uint2*)h;
    }
}

// ---------------- temporal attention (scalar, fp16 output) ----------------
__global__ __launch_bounds__(128) void temporal_attn_kernel(
    const float* __restrict__ qkv, __half* __restrict__ oh)
{
    __shared__ __align__(16) float sq[Tdim][388];
    const int bn  = blockIdx.x;
    const int b   = bn / Ndim;
    const int n   = bn % Ndim;
    const int tid = threadIdx.x;

    for (int idx = tid; idx < Tdim * 96; idx += 128) {
        int t = idx / 96;
        int c = (idx % 96) * 4;
        size_t rr = ((size_t)(b * Tdim + t) * Ndim + n) * 384;
        *(float4*)&sq[t][c] = *(const float4*)(qkv + rr + c);
    }
    __syncthreads();

    if (tid < Hdim * Tdim) {
        const int h   = tid / Tdim;
        const int q   = tid % Tdim;
        const int off = h * 16;
        float qd[16];
#pragma unroll
        for (int d = 0; d < 16; d++) qd[d] = sq[q][off + d];
        float e[Tdim], Z = 0.0f;
#pragma unroll
        for (int s = 0; s < Tdim; s++) {
            float sc = 0.0f;
#pragma unroll
            for (int d = 0; d < 16; d++) sc = fmaf(qd[d], sq[s][128 + off + d], sc);
            e[s] = __expf(sc * 0.25f);
            Z += e[s];
        }
        float inv = 1.0f / Z;
        __half hv[16];
#pragma unroll
        for (int d = 0; d < 16; d++) {
            float a = 0.0f;
#pragma unroll
            for (int s = 0; s < Tdim; s++) a = fmaf(e[s], sq[s][256 + off + d], a);
            hv[d] = __float2half(a * inv);
        }
        size_t ro = ((size_t)(b * Tdim + q) * Ndim + n) * 128 + off;
        *(uint4*)(oh + ro)     = *(uint4*)&hv[0];
        *(uint4*)(oh + ro + 8) = *(uint4*)&hv[8];
    }
}

// ---------------- spatial attention: single-fp16 HMMA flash (no-max softmax) ----------------
// smem: Q 0 (6144) | K 6144 (18432) | VT 24576 (12544) | bias 37120 (33792) = 70912
#define SA_SMEM 70912

__global__ __launch_bounds__(256, 2) void spatial_attn_mma_kernel(
    const float* __restrict__ qkv, const float* __restrict__ gbias,
    __half* __restrict__ oh)
{
    extern __shared__ __align__(16) char smem[];
    __half* sp = (__half*)smem;
    float* bs = (float*)(smem + 37120);
    const uint32_t sb = smem_u32(smem);

    const int h   = blockIdx.x;
    const int bt  = blockIdx.y;
    const int q0  = blockIdx.z * 128;
    const int tid = threadIdx.x;
    const int w   = tid >> 5, l = tid & 31;
    const int g   = l >> 2, tig = l & 3;
    const size_t base = (size_t)bt * Ndim * 384;

    for (int e = tid; e < 2048; e += 256) {
        int row = e >> 4, d = e & 15;
        float v = (q0 + row < Ndim) ? qkv[base + (size_t)(q0 + row) * 384 + h * 16 + d] : 0.f;
        sp[row * 24 + d] = __float2half(v);
    }
    for (int e = tid; e < 6144; e += 256) {
        int row = e >> 4, d = e & 15;
        float kv = (row < Ndim) ? qkv[base + (size_t)row * 384 + 128 + h * 16 + d] : 0.f;
        sp[3072 + row * 24 + d] = __float2half(kv);
        float vv = (row < Ndim) ? qkv[base + (size_t)row * 384 + 256 + h * 16 + d] : 0.f;
        sp[12288 + d * 392 + row] = __float2half(vv);
    }
    __syncthreads();

    const uint32_t laneA = (uint32_t)((((l >> 3) & 1) * 8 + (l & 7)) * 48 + ((l >> 4) & 1) * 16);
    const uint32_t laneB = (uint32_t)((((l >> 4) & 1) * 8 + (l & 7)) * 48 + ((l >> 3) & 1) * 16);
    const uint32_t laneV = (uint32_t)((((l >> 4) & 1) * 8 + (l & 7)) * 784 + ((l >> 3) & 1) * 16);

    uint32_t q4[4];
    ldm4(q4, sb + (uint32_t)(w * 16) * 48 + laneA);

    float o0[4] = {0.f, 0.f, 0.f, 0.f}, o1[4] = {0.f, 0.f, 0.f, 0.f};
    float zg = 0.f, zh = 0.f;
    const int r0 = w * 16 + g, r1 = r0 + 8;

    for (int ch = 0; ch < 6; ch++) {
        __syncthreads();
        for (int e = tid; e < 8192; e += 256) {
            int row = e >> 6, col = e & 63;
            int qq = q0 + row, jj = ch * 64 + col;
            bs[row * 66 + col] = (qq < Ndim && jj < Ndim) ? gbias[qq * Ndim + jj] : 0.f;
        }
        __syncthreads();

        float s[8][4];
#pragma unroll
        for (int t = 0; t < 8; t++)
#pragma unroll
            for (int k = 0; k < 4; k++) s[t][k] = 0.f;
#pragma unroll
        for (int i = 0; i < 4; i++) {
            uint32_t k4[4];
            ldm4(k4, sb + 6144 + (uint32_t)(ch * 64 + i * 16) * 48 + laneB);
            mma_f16(s[2 * i],     q4, &k4[0]);
            mma_f16(s[2 * i + 1], q4, &k4[2]);
        }

        uint32_t pa[4][4];
#pragma unroll
        for (int t = 0; t < 8; t++) {
            const int f = t >> 1, hf = t & 1;
            const int jl = f * 16 + hf * 8 + 2 * tig;
            const int jglob = ch * 64 + jl;
            float p0 = (jglob     < Ndim) ? __expf(fmaf(s[t][0], 0.25f, bs[r0 * 66 + jl]))     : 0.f;
            float p1 = (jglob + 1 < Ndim) ? __expf(fmaf(s[t][1], 0.25f, bs[r0 * 66 + jl + 1])) : 0.f;
            float p2 = (jglob     < Ndim) ? __expf(fmaf(s[t][2], 0.25f, bs[r1 * 66 + jl]))     : 0.f;
            float p3 = (jglob + 1 < Ndim) ? __expf(fmaf(s[t][3], 0.25f, bs[r1 * 66 + jl + 1])) : 0.f;
            zg += p0 + p1; zh += p2 + p3;
            pa[f][hf * 2 + 0] = pkh(__float2half(p0), __float2half(p1));
            pa[f][hf * 2 + 1] = pkh(__float2half(p2), __float2half(p3));
        }

#pragma unroll
        for (int kf = 0; kf < 4; kf++) {
            uint32_t v4[4];
            ldm4(v4, sb + 24576 + laneV + (uint32_t)(ch * 64 + kf * 16) * 2);
            mma_f16(o0, pa[kf], &v4[0]);
            mma_f16(o1, pa[kf], &v4[2]);
        }
    }

    zg += __shfl_xor_sync(0xffffffffu, zg, 1);
    zg += __shfl_xor_sync(0xffffffffu, zg, 2);
    zh += __shfl_xor_sync(0xffffffffu, zh, 1);
    zh += __shfl_xor_sync(0xffffffffu, zh, 2);
    const float ig = 1.f / zg, ih = 1.f / zh;

    const int qg = q0 + r0;
    if (qg < Ndim) {
        size_t rb = ((size_t)bt * Ndim + qg) * 128 + h * 16;
        *(uint32_t*)(oh + rb + 2 * tig)     = pkh(__float2half(o0[0] * ig), __float2half(o0[1] * ig));
        *(uint32_t*)(oh + rb + 8 + 2 * tig) = pkh(__float2half(o1[0] * ig), __float2half(o1[1] * ig));
    }
    const int qh8 = q0 + r1;
    if (qh8 < Ndim) {
        size_t rb = ((size_t)bt * Ndim + qh8) * 128 + h * 16;
        *(uint32_t*)(oh + rb + 2 * tig)     = pkh(__float2half(o0[2] * ih), __float2half(o0[3] * ih));
        *(uint32_t*)(oh + rb + 8 + 2 * tig) = pkh(__float2half(o1[2] * ih), __float2half(o1[3] * ih));
    }
}

// ---------------- launch ----------------
extern "C" void kernel_launch(void* const* d_in, const int* in_sizes, int n_in,
                              void* d_out, int out_size)
{
    const float* x       = (const float*)d_in[0];
    const float* t_w_in  = (const float*)d_in[1];
    const float* t_b_in  = (const float*)d_in[2];
    const float* t_w_out = (const float*)d_in[3];
    const float* t_b_out = (const float*)d_in[4];
    const float* s_w_in  = (const float*)d_in[5];
    const float* s_b_in  = (const float*)d_in[6];
    const float* s_w_out = (const float*)d_in[7];
    const float* s_b_out = (const float*)d_in[8];
    const float* gbias   = (const float*)d_in[9];
    const float* ntg     = (const float*)d_in[10];
    const float* ntb     = (const float*)d_in[11];
    const float* nsg     = (const float*)d_in[12];
    const float* nsb     = (const float*)d_in[13];
    const float* ffw1    = (const float*)d_in[14];
    const float* ffb1    = (const float*)d_in[15];
    const float* ffw2    = (const float*)d_in[16];
    const float* ffb2    = (const float*)d_in[17];
    const float* nfg     = (const float*)d_in[18];
    const float* nfb     = (const float*)d_in[19];
    float* out = (float*)d_out;

    float *qkv, *x1f, *x2f;
    __half *xh, *ah, *bh, *hh, *wh;
    cudaGetSymbolAddress((void**)&qkv, g_qkv);
    cudaGetSymbolAddress((void**)&x1f, g_x1f);
    cudaGetSymbolAddress((void**)&x2f, g_x2f);
    cudaGetSymbolAddress((void**)&xh, g_xh);
    cudaGetSymbolAddress((void**)&ah, g_ah);
    cudaGetSymbolAddress((void**)&bh, g_bh);
    cudaGetSymbolAddress((void**)&hh, g_hh);
    cudaGetSymbolAddress((void**)&wh, g_wh);

    cudaFuncSetAttribute(mm_kernel<128, 0, false>, cudaFuncAttributeMaxDynamicSharedMemorySize, SMEM_DYN);
    cudaFuncSetAttribute(mm_kernel<128, 1, false>, cudaFuncAttributeMaxDynamicSharedMemorySize, SMEM_DYN);
    cudaFuncSetAttribute(mm_kernel<128, 2, true >, cudaFuncAttributeMaxDynamicSharedMemorySize, SMEM_DYN);
    cudaFuncSetAttribute(mm_kernel<512, 2, false>, cudaFuncAttributeMaxDynamicSharedMemorySize, SMEM_DYN);
    cudaFuncSetAttribute(spatial_attn_mma_kernel, cudaFuncAttributeMaxDynamicSharedMemorySize, SA_SMEM);

    // converts (phase 1-6 weights first)
    convert_h_kernel<<<(BTN * 128 / 4 + 255) / 256, 256>>>(x, xh, BTN * 128 / 4);
    convert_h_kernel<<<48, 256>>>(t_w_in,  wh + WOFF_TIN,  49152 / 4);
    convert_h_kernel<<<16, 256>>>(t_w_out, wh + WOFF_TOUT, 16384 / 4);
    convert_h_kernel<<<48, 256>>>(s_w_in,  wh + WOFF_SIN,  49152 / 4);
    convert_h_kernel<<<16, 256>>>(s_w_out, wh + WOFF_SOUT, 16384 / 4);

    // 1) temporal QKV
    mm_kernel<128, 0, false><<<dim3(3, MTILES), 256, SMEM_DYN>>>(
        xh, wh + WOFF_TIN, t_b_in, nullptr, nullptr, nullptr, qkv, nullptr, 384);
    // 2) temporal attention -> fp16
    temporal_attn_kernel<<<BNSEQ, 128>>>(qkv, ah);
    // 3) temporal out-proj + res + LN -> x1 fp32 + fp16 (bh)
    mm_kernel<128, 2, true><<<dim3(1, MTILES), 256, SMEM_DYN>>>(
        ah, wh + WOFF_TOUT, t_b_out, x, ntg, ntb, x1f, bh, 128);
    // 4) spatial QKV
    mm_kernel<128, 0, false><<<dim3(3, MTILES), 256, SMEM_DYN>>>(
        bh, wh + WOFF_SIN, s_b_in, nullptr, nullptr, nullptr, qkv, nullptr, 384);
    // 5) spatial attention (fp16 HMMA) -> fp16
    spatial_attn_mma_kernel<<<dim3(Hdim, BTSEQ, 3), 256, SA_SMEM>>>(qkv, gbias, ah);
    // 6) spatial out-proj + res + LN -> x2 fp32 + fp16 (reuse xh)
    mm_kernel<128, 2, true><<<dim3(1, MTILES), 256, SMEM_DYN>>>(
        ah, wh + WOFF_SOUT, s_b_out, x1f, nsg, nsb, x2f, xh, 128);
    // converts for FFN weights
    convert_h_kernel<<<64, 256>>>(ffw1, wh + WOFF_FF1, 65536 / 4);
    convert_h_kernel<<<64, 256>>>(ffw2, wh + WOFF_FF2, 65536 / 4);
    // 7) FFN up + GELU -> fp16 hh
    mm_kernel<128, 1, false><<<dim3(4, MTILES), 256, SMEM_DYN>>>(
        xh, wh + WOFF_FF1, ffb1, nullptr, nullptr, nullptr, nullptr, hh, 512);
    // 8) FFN down + res + LN -> final output
    mm_kernel<512, 2, false><<<dim3(1, MTILES), 256, SMEM_DYN>>>(
        hh, wh + WOFF_FF2, ffb2, x2f, nfg, nfb, out, nullptr, 128);
}